// round 13
// baseline (speedup 1.0000x reference)
#include <cuda_runtime.h>
#include <cuda_bf16.h>
#include <math.h>
#include <stdint.h>

// Problem constants
#define Hd   512
#define G4   2048      // 4*H
#define Ed   250
#define Bd   32
#define NCd  5
#define Td   20
#define Rd   160       // NC*B
#define Vd   30522
#define CNNd 2048
#define Md   3200      // NC*T*B
#define Kfc  1024      // 2*H
#define PITCH 40       // smem row pitch in bf16 elems (80B, bank-conflict-free)
#define NBLK 128       // persistent chain blocks (all co-resident)

// ---------------- device scratch (no allocations allowed) ----------------
__device__ float g_WihP0[2][Ed][G4];
__device__ float g_bP0[2][G4];
__device__ float g_bP1[2][G4];
__device__ float g_X0[2][Td][Rd][G4];        // layer0 input projections (+bias)
__device__ float g_Z[2][Td][Rd][G4];         // layer1 input projections (+bias)
__device__ float g_cS[2][2][Rd][Hd];         // [layer][dir][row][h]  fp32 cell state
// LSTM h state as bf16 hi/lo, double buffered: [parity][layer][dir][row][h]
__device__ __nv_bfloat16 g_hbH[2][2][2][Rd][Hd];
__device__ __nv_bfloat16 g_hbL[2][2][2][Rd][Hd];
// bf16 hi/lo split activations (A operands for mma GEMMs)
__device__ __nv_bfloat16 g_hsH[2][Td][Rd][Hd];
__device__ __nv_bfloat16 g_hsL[2][Td][Rd][Hd];
__device__ __nv_bfloat16 g_packedH[Md][Kfc];
__device__ __nv_bfloat16 g_packedL[Md][Kfc];
// bf16 hi/lo split weights (B operands, K-major rows)
__device__ __nv_bfloat16 g_WfcH[(long)Vd * Kfc];
__device__ __nv_bfloat16 g_WfcL[(long)Vd * Kfc];
__device__ __nv_bfloat16 g_W1H[2L * G4 * Kfc];   // gate-interleaved [d][n][k]
__device__ __nv_bfloat16 g_W1L[2L * G4 * Kfc];
__device__ __nv_bfloat16 g_WsH[2][2][G4][Hd];    // recurrent weights [lay][d][n][k]
__device__ __nv_bfloat16 g_WsL[2][2][G4][Hd];
// software grid barrier state (replay-safe: cnt returns to 0, gen monotonic)
__device__ unsigned g_bar_cnt = 0;
__device__ unsigned g_bar_gen = 0;

__device__ __forceinline__ uint32_t smem_u32(const void* p) {
    uint32_t a;
    asm("{ .reg .u64 t; cvta.to.shared.u64 t, %1; cvt.u32.u64 %0, t; }"
        : "=r"(a) : "l"(p));
    return a;
}
#define LDSM4(r, addr) \
    asm volatile("ldmatrix.sync.aligned.m8n8.x4.shared.b16 {%0,%1,%2,%3}, [%4];" \
        : "=r"((r)[0]), "=r"((r)[1]), "=r"((r)[2]), "=r"((r)[3]) : "r"(addr))
#define MMA16816(c, a, b) \
    asm volatile("mma.sync.aligned.m16n8k16.row.col.f32.bf16.bf16.f32 " \
        "{%0,%1,%2,%3}, {%4,%5,%6,%7}, {%8,%9}, {%0,%1,%2,%3};" \
        : "+f"((c)[0]), "+f"((c)[1]), "+f"((c)[2]), "+f"((c)[3]) \
        : "r"((a)[0]), "r"((a)[1]), "r"((a)[2]), "r"((a)[3]), "r"((b)[0]), "r"((b)[1]))

// ---- FFMA-only activations (the per-step bottleneck was MUFU, rt=8/SMSP) ----
// fsig(x) = 1/(1 + 2^(-x*log2e)); 2^u = 2^round(u) * poly(frac); reciprocal via
// magic constant + 3 Newton steps. rel err ~1.5e-7. Zero MUFU instructions.
__device__ __forceinline__ float fsig(float x) {
    float u = fminf(fmaxf(-1.4426950408889634f * x, -80.f), 80.f);
    int e = __float2int_rn(u);
    float f = u - (float)e;
    float p = fmaf(1.5403530e-4f, f, 1.3333558e-3f);
    p = fmaf(p, f, 9.6181291e-3f);
    p = fmaf(p, f, 5.5504109e-2f);
    p = fmaf(p, f, 2.4022651e-1f);
    p = fmaf(p, f, 6.9314718e-1f);
    p = fmaf(p, f, 1.0f);
    float s = __int_as_float((e + 127) << 23);       // 2^e (|e|<=80: normal)
    float den = fmaf(p, s, 1.0f);                    // 1 + 2^u  (den >= 1)
    float r = __int_as_float(0x7EF311C3 - __float_as_int(den));
    r = r * fmaf(-den, r, 2.0f);
    r = r * fmaf(-den, r, 2.0f);
    r = r * fmaf(-den, r, 2.0f);
    return r;
}
__device__ __forceinline__ float ftanh(float x) {
    return fmaf(2.0f, fsig(2.0f * x), -1.0f);
}

// ---- grid barrier (all NBLK blocks must be resident) ----
__device__ __forceinline__ void gbar() {
    __syncthreads();
    if (threadIdx.x == 0) {
        __threadfence();
        unsigned gen = atomicAdd(&g_bar_gen, 0u);
        if (atomicAdd(&g_bar_cnt, 1u) == NBLK - 1) {
            atomicExch(&g_bar_cnt, 0u);
            __threadfence();
            atomicAdd(&g_bar_gen, 1u);
        } else {
            while (atomicAdd(&g_bar_gen, 0u) == gen) __nanosleep(64);
        }
        __threadfence();
    }
    __syncthreads();
}

// ---------------- weight packing (fp32 for xproj, biases) ----------------
__global__ void k_pack(const float* __restrict__ Wih0,
                       const float* __restrict__ bih0, const float* __restrict__ bhh0,
                       const float* __restrict__ bih1, const float* __restrict__ bhh1) {
    int region = blockIdx.y;
    long i = (long)blockIdx.x * blockDim.x + threadIdx.x;
    if (region == 0) {
        if (i >= 2L * Ed * G4) return;
        int d = (int)(i / (Ed * G4)); int rem = (int)(i % (Ed * G4));
        int k = rem / G4, n = rem % G4;
        int h = n >> 2, g = n & 3;
        g_WihP0[d][k][n] = Wih0[((long)d * G4 + g * Hd + h) * Ed + k];
    } else if (region == 1) {
        if (i >= 2L * G4) return;
        int d = (int)(i / G4); int n = (int)(i % G4);
        int h = n >> 2, g = n & 3;
        long j = (long)d * G4 + g * Hd + h;
        g_bP0[d][n] = bih0[j] + bhh0[j];
    } else {
        if (i >= 2L * G4) return;
        int d = (int)(i / G4); int n = (int)(i % G4);
        int h = n >> 2, g = n & 3;
        long j = (long)d * G4 + g * Hd + h;
        g_bP1[d][n] = bih1[j] + bhh1[j];
    }
}

// ---------------- bf16 hi/lo split packing ----------------
__global__ void k_packbf(const float* __restrict__ Wfc, const float* __restrict__ Wih1,
                         const float* __restrict__ Whh0, const float* __restrict__ Whh1) {
    long i = (long)blockIdx.x * blockDim.x + threadIdx.x;
    if (blockIdx.y == 0) {
        if (i >= (long)Vd * Kfc) return;
        float x = Wfc[i];
        __nv_bfloat16 h = __float2bfloat16(x);
        g_WfcH[i] = h;
        g_WfcL[i] = __float2bfloat16(x - __bfloat162float(h));
    } else if (blockIdx.y == 1) {
        if (i >= 2L * G4 * Kfc) return;
        int d = (int)(i / (G4 * Kfc)); long rem = i % ((long)G4 * Kfc);
        int n = (int)(rem / Kfc), k = (int)(rem % Kfc);
        int h = n >> 2, g = n & 3;
        float x = Wih1[((long)d * G4 + g * Hd + h) * Kfc + k];
        __nv_bfloat16 hb = __float2bfloat16(x);
        g_W1H[i] = hb;
        g_W1L[i] = __float2bfloat16(x - __bfloat162float(hb));
    } else {
        if (i >= 2L * 2 * G4 * Hd) return;
        int lay = (int)(i / (2L * G4 * Hd));
        long rem = i % (2L * G4 * Hd);
        int d = (int)(rem / ((long)G4 * Hd));
        long r2 = rem % ((long)G4 * Hd);
        int n = (int)(r2 / Hd), k = (int)(r2 % Hd);
        int h = n >> 2, g = n & 3;
        const float* W = lay ? Whh1 : Whh0;
        float x = W[((long)d * G4 + g * Hd + h) * Hd + k];
        __nv_bfloat16 hb = __float2bfloat16(x);
        g_WsH[lay][d][n][k] = hb;
        g_WsL[lay][d][n][k] = __float2bfloat16(x - __bfloat162float(hb));
    }
}

// ---------------- initial states: bf16 hi/lo h0, fp32 c0 ----------------
__global__ void k_init(const float* __restrict__ img, const float* __restrict__ Wh,
                       const float* __restrict__ bh, const float* __restrict__ Wc,
                       const float* __restrict__ bc) {
    int i = blockIdx.x * blockDim.x + threadIdx.x;
    if (i >= 2 * Bd * Hd) return;
    int which = i / (Bd * Hd);
    int rem = i % (Bd * Hd);
    int b = rem / Hd, j = rem % Hd;
    const float* W = which ? Wc : Wh;
    const float* bias = which ? bc : bh;
    const float4* a4 = (const float4*)(img + (long)b * CNNd);
    const float4* w4 = (const float4*)(W + (long)j * CNNd);
    float acc = 0.f;
#pragma unroll 4
    for (int k = 0; k < CNNd / 4; k++) {
        float4 a = a4[k], w = w4[k];
        acc += a.x * w.x + a.y * w.y + a.z * w.z + a.w * w.w;
    }
    float v = fmaxf(acc + bias[j], 0.f);
    __nv_bfloat16 hv = __float2bfloat16(v);
    __nv_bfloat16 lv = __float2bfloat16(v - __bfloat162float(hv));
    for (int nc = 0; nc < NCd; nc++) {
        int row = nc * Bd + b;
        for (int l = 0; l < 2; l++)
            for (int d = 0; d < 2; d++) {
                if (which == 0) { g_hbH[0][l][d][row][j] = hv; g_hbL[0][l][d][row][j] = lv; }
                else            g_cS[l][d][row][j] = v;
            }
    }
}

// ---------------- layer0 input projections for all t ----------------
__global__ void k_xproj(const float* __restrict__ emb, const int* __restrict__ cap) {
    __shared__ float xs[32 * Ed];
    __shared__ int toks[32];
    int bm = blockIdx.x, bn = blockIdx.y, d = blockIdx.z;
    int tid = threadIdx.x;
    if (tid < 32) {
        int m = bm * 32 + tid;
        int t = m / Rd, r = m % Rd;
        int nc = r >> 5, b = r & 31;
        toks[tid] = cap[b * (NCd * Td) + nc * Td + t];
    }
    __syncthreads();
    for (int e = tid; e < 32 * Ed; e += 256) {
        int lr = e / Ed, k = e % Ed;
        xs[e] = emb[(long)toks[lr] * Ed + k];
    }
    __syncthreads();
    int tx = tid & 31, ty = tid >> 5;
    float acc[4][4];
#pragma unroll
    for (int a = 0; a < 4; a++)
#pragma unroll
        for (int c = 0; c < 4; c++) acc[a][c] = 0.f;
    int n0 = bn * 128;
    const float* Bp = &g_WihP0[d][0][0];
#pragma unroll 5
    for (int k = 0; k < Ed; k++) {
        float av[4], bv[4];
#pragma unroll
        for (int jr = 0; jr < 4; jr++) av[jr] = xs[(ty + jr * 8) * Ed + k];
#pragma unroll
        for (int jc = 0; jc < 4; jc++) bv[jc] = Bp[(long)k * G4 + n0 + tx + jc * 32];
#pragma unroll
        for (int jr = 0; jr < 4; jr++)
#pragma unroll
            for (int jc = 0; jc < 4; jc++) acc[jr][jc] += av[jr] * bv[jc];
    }
    int m0 = bm * 32;
#pragma unroll
    for (int jr = 0; jr < 4; jr++) {
        int m = m0 + ty + jr * 8;
        int t = m / Rd, r = m % Rd;
#pragma unroll
        for (int jc = 0; jc < 4; jc++) {
            int n = n0 + tx + jc * 32;
            g_X0[d][t][r][n] = acc[jr][jc] + g_bP0[d][n];
        }
    }
}

// =========================================================================
// chain device pieces: shared smem layout for 320-thread persistent blocks
// =========================================================================
#define A_ELEMS (2 * 160 * PITCH)
#define B_ELEMS (2 * 128 * PITCH)
#define CHAIN_SMEM ((2 * A_ELEMS + 2 * B_ELEMS) * 2)

// ---- one recurrent LSTM step tile: block tile 160x64, warp 32x32 (5m x 2n) ----
__device__ __forceinline__ void do_step(char* dsm, int n0, int lay, int d,
                                        int p, int s, int w) {
    __nv_bfloat16* sA_h = (__nv_bfloat16*)dsm;
    __nv_bfloat16* sA_l = sA_h + A_ELEMS;
    __nv_bfloat16* sB_h = sA_l + A_ELEMS;
    __nv_bfloat16* sB_l = sB_h + B_ELEMS;
    uint32_t uAh = smem_u32(sA_h), uAl = smem_u32(sA_l);
    uint32_t uBh = smem_u32(sB_h), uBl = smem_u32(sB_l);

    int tid = threadIdx.x;
    int lane = tid & 31, wid = tid >> 5;
    int wm = wid >> 1, wn = wid & 1;

    const __nv_bfloat16* hH = &g_hbH[p][lay][d][0][0];
    const __nv_bfloat16* hL = &g_hbL[p][lay][d][0][0];
    __nv_bfloat16* hoH = &g_hbH[p ^ 1][lay][d][0][0];
    __nv_bfloat16* hoL = &g_hbL[p ^ 1][lay][d][0][0];
    float* cstp = &g_cS[lay][d][0][0];
    int xidx = d ? (w - s) : s;
    const float* Xp = lay ? &g_Z[d][xidx][0][0] : &g_X0[d][xidx][0][0];
    const __nv_bfloat16* BH = &g_WsH[lay][d][0][0];
    const __nv_bfloat16* BL = &g_WsL[lay][d][0][0];

    int arow = (tid >= 160) ? tid - 160 : tid;
    int ak0 = (tid >= 160) ? 16 : 0;
    int brow = tid >> 1, bk0 = (tid & 1) * 16;

    float c[2][4][4];
#pragma unroll
    for (int mt = 0; mt < 2; mt++)
#pragma unroll
        for (int nt = 0; nt < 4; nt++)
#pragma unroll
            for (int q = 0; q < 4; q++) c[mt][nt][q] = 0.f;

    uint4 vA[4], vB[4];

    auto LOAD = [&](int kc) {
        int ka = kc * 32 + ak0;
        vA[0] = *(const uint4*)(hH + arow * Hd + ka);
        vA[1] = *(const uint4*)(hH + arow * Hd + ka + 8);
        vA[2] = *(const uint4*)(hL + arow * Hd + ka);
        vA[3] = *(const uint4*)(hL + arow * Hd + ka + 8);
        if (tid < 128) {
            long bo = (long)(n0 + brow) * Hd + kc * 32 + bk0;
            vB[0] = *(const uint4*)(BH + bo);
            vB[1] = *(const uint4*)(BH + bo + 8);
            vB[2] = *(const uint4*)(BL + bo);
            vB[3] = *(const uint4*)(BL + bo + 8);
        }
    };
    auto STORE = [&](int buf) {
        int sa = buf * 160 * PITCH + arow * PITCH + ak0;
        *(uint4*)&sA_h[sa] = vA[0]; *(uint4*)&sA_h[sa + 8] = vA[1];
        *(uint4*)&sA_l[sa] = vA[2]; *(uint4*)&sA_l[sa + 8] = vA[3];
        if (tid < 128) {
            int sbb = buf * 64 * PITCH + brow * PITCH + bk0;
            *(uint4*)&sB_h[sbb] = vB[0]; *(uint4*)&sB_h[sbb + 8] = vB[1];
            *(uint4*)&sB_l[sbb] = vB[2]; *(uint4*)&sB_l[sbb + 8] = vB[3];
        }
    };
    auto COMPUTE = [&](int buf) {
        uint32_t boA = (uint32_t)buf * 160 * PITCH * 2;
        uint32_t boB = (uint32_t)buf * 64 * PITCH * 2;
#pragma unroll
        for (int k16 = 0; k16 < 2; k16++) {
            int ar = lane & 15;
            int acs = k16 * 16 + ((lane >> 4) << 3);
            uint32_t ah[2][4], al[2][4];
#pragma unroll
            for (int mt = 0; mt < 2; mt++) {
                uint32_t off = boA + (uint32_t)((wm * 32 + mt * 16 + ar) * PITCH + acs) * 2;
                LDSM4(ah[mt], uAh + off);
                LDSM4(al[mt], uAl + off);
            }
            int br = (lane & 7) + ((lane >> 4) << 3);
            int bcs = k16 * 16 + (((lane >> 3) & 1) << 3);
            uint32_t bh[4][2], bl[4][2];
#pragma unroll
            for (int ntp = 0; ntp < 2; ntp++) {
                uint32_t off = boB + (uint32_t)((wn * 32 + ntp * 16 + br) * PITCH + bcs) * 2;
                uint32_t r4[4];
                LDSM4(r4, uBh + off);
                bh[ntp * 2][0] = r4[0]; bh[ntp * 2][1] = r4[1];
                bh[ntp * 2 + 1][0] = r4[2]; bh[ntp * 2 + 1][1] = r4[3];
                LDSM4(r4, uBl + off);
                bl[ntp * 2][0] = r4[0]; bl[ntp * 2][1] = r4[1];
                bl[ntp * 2 + 1][0] = r4[2]; bl[ntp * 2 + 1][1] = r4[3];
            }
#pragma unroll
            for (int mt = 0; mt < 2; mt++)
#pragma unroll
                for (int nt = 0; nt < 4; nt++) {
                    MMA16816(c[mt][nt], ah[mt], bh[nt]);
                    MMA16816(c[mt][nt], ah[mt], bl[nt]);
                    MMA16816(c[mt][nt], al[mt], bh[nt]);
                }
        }
    };

    LOAD(0); STORE(0);
    __syncthreads();
    for (int kc = 0; kc < 16; kc++) {
        int buf = kc & 1;
        if (kc < 15) LOAD(kc + 1);
        COMPUTE(buf);
        if (kc < 15) STORE(buf ^ 1);
        __syncthreads();
    }

    // ---- fused LSTM cell epilogue: FFMA-only activations, ALL lanes active ----
    // quad pair (q, q^1) shares one h-unit: q holds (i,f) rows r1/r2, q^1 holds
    // (g,o). After shuffle-xor(1): IF lane owns row r1, GO lane owns row r2.
    int qrow = lane >> 2, quad = lane & 3;
    bool isIF = (quad & 1) == 0;
#pragma unroll
    for (int mt = 0; mt < 2; mt++) {
#pragma unroll
        for (int nt = 0; nt < 4; nt++) {
            int nbase = n0 + wn * 32 + nt * 8;
            int n = nbase + quad * 2;
            int r1 = wm * 32 + mt * 16 + qrow;
            int r2 = r1 + 8;
            float2 x1 = *(const float2*)&Xp[(long)r1 * G4 + n];
            float2 x2 = *(const float2*)&Xp[(long)r2 * G4 + n];
            float a0 = c[mt][nt][0] + x1.x;
            float a1 = c[mt][nt][1] + x1.y;
            float a2 = c[mt][nt][2] + x2.x;
            float a3 = c[mt][nt][3] + x2.y;
            float b0 = __shfl_xor_sync(0xffffffffu, a0, 1);
            float b1 = __shfl_xor_sync(0xffffffffu, a1, 1);
            float b2 = __shfl_xor_sync(0xffffffffu, a2, 1);
            float b3 = __shfl_xor_sync(0xffffffffu, a3, 1);
            int hh = (nbase >> 2) + (quad >> 1);
            int row = isIF ? r1 : r2;
            float gi = isIF ? a0 : b2;
            float gf = isIF ? a1 : b3;
            float gg = isIF ? b0 : a2;
            float go = isIF ? b1 : a3;
            float si = fsig(gi);
            float sf = fsig(gf);
            float so = fsig(go);
            float tg = ftanh(gg);
            float cc = fmaf(sf, cstp[row * Hd + hh], si * tg);
            float h = so * ftanh(cc);
            cstp[row * Hd + hh] = cc;
            __nv_bfloat16 hb = __float2bfloat16(h);
            __nv_bfloat16 lb = __float2bfloat16(h - __bfloat162float(hb));
            hoH[row * Hd + hh] = hb;
            hoL[row * Hd + hh] = lb;
            if (lay == 0) {
                g_hsH[d][s][row][hh] = hb;
                g_hsL[d][s][row][hh] = lb;
            }
        }
    }
}

// ---- one zproj tile: 160x128, warp tile 32x64 (5m x 2n), K=1024 ----
__device__ __forceinline__ void do_zproj(char* dsm, int t, int d, int nt, int w) {
    __nv_bfloat16* sA_h = (__nv_bfloat16*)dsm;
    __nv_bfloat16* sA_l = sA_h + A_ELEMS;
    __nv_bfloat16* sB_h = sA_l + A_ELEMS;
    __nv_bfloat16* sB_l = sB_h + B_ELEMS;
    uint32_t uAh = smem_u32(sA_h), uAl = smem_u32(sA_l);
    uint32_t uBh = smem_u32(sB_h), uBl = smem_u32(sB_l);

    int tid = threadIdx.x;
    int lane = tid & 31, wid = tid >> 5;
    int wm = wid >> 1, wn = wid & 1;
    int n0 = nt * 128;
    int tb = w - t;

    int arow = (tid >= 160) ? tid - 160 : tid;
    int ak0 = (tid >= 160) ? 16 : 0;
    int brow = tid >> 1, bk0 = (tid & 1) * 16;   // tid < 256

    float c[2][8][4];
#pragma unroll
    for (int mt = 0; mt < 2; mt++)
#pragma unroll
        for (int ntf = 0; ntf < 8; ntf++)
#pragma unroll
            for (int q = 0; q < 4; q++) c[mt][ntf][q] = 0.f;

    uint4 vA[4], vB[4];

    auto LOAD = [&](int kc) {
        int ka = kc * 32 + ak0;
        const __nv_bfloat16* pH = (ka < Hd) ? &g_hsH[0][t][arow][ka]
                                            : &g_hsH[1][tb][arow][ka - Hd];
        const __nv_bfloat16* pL = (ka < Hd) ? &g_hsL[0][t][arow][ka]
                                            : &g_hsL[1][tb][arow][ka - Hd];
        vA[0] = *(const uint4*)pH;
        vA[1] = *(const uint4*)(pH + 8);
        vA[2] = *(const uint4*)pL;
        vA[3] = *(const uint4*)(pL + 8);
        if (tid < 256) {
            long bo = ((long)d * G4 + n0 + brow) * Kfc + kc * 32 + bk0;
            vB[0] = *(const uint4*)(g_W1H + bo);
            vB[1] = *(const uint4*)(g_W1H + bo + 8);
            vB[2] = *(const uint4*)(g_W1L + bo);
            vB[3] = *(const uint4*)(g_W1L + bo + 8);
        }
    };
    auto STORE = [&](int buf) {
        int sa = buf * 160 * PITCH + arow * PITCH + ak0;
        *(uint4*)&sA_h[sa] = vA[0]; *(uint4*)&sA_h[sa + 8] = vA[1];
        *(uint4*)&sA_l[sa] = vA[2]; *(uint4*)&sA_l[sa + 8] = vA[3];
        if (tid < 256) {
            int sbb = buf * 128 * PITCH + brow * PITCH + bk0;
            *(uint4*)&sB_h[sbb] = vB[0]; *(uint4*)&sB_h[sbb + 8] = vB[1];
            *(uint4*)&sB_l[sbb] = vB[2]; *(uint4*)&sB_l[sbb + 8] = vB[3];
        }
    };
    auto COMPUTE = [&](int buf) {
        uint32_t boA = (uint32_t)buf * 160 * PITCH * 2;
        uint32_t boB = (uint32_t)buf * 128 * PITCH * 2;
#pragma unroll
        for (int k16 = 0; k16 < 2; k16++) {
            int ar = lane & 15;
            int acs = k16 * 16 + ((lane >> 4) << 3);
            uint32_t ah[2][4], al[2][4];
#pragma unroll
            for (int mt = 0; mt < 2; mt++) {
                uint32_t off = boA + (uint32_t)((wm * 32 + mt * 16 + ar) * PITCH + acs) * 2;
                LDSM4(ah[mt], uAh + off);
                LDSM4(al[mt], uAl + off);
            }
            int br = (lane & 7) + ((lane >> 4) << 3);
            int bcs = k16 * 16 + (((lane >> 3) & 1) << 3);
            uint32_t bh[8][2], bl[8][2];
#pragma unroll
            for (int ntp = 0; ntp < 4; ntp++) {
                uint32_t off = boB + (uint32_t)((wn * 64 + ntp * 16 + br) * PITCH + bcs) * 2;
                uint32_t r4[4];
                LDSM4(r4, uBh + off);
                bh[ntp * 2][0] = r4[0]; bh[ntp * 2][1] = r4[1];
                bh[ntp * 2 + 1][0] = r4[2]; bh[ntp * 2 + 1][1] = r4[3];
                LDSM4(r4, uBl + off);
                bl[ntp * 2][0] = r4[0]; bl[ntp * 2][1] = r4[1];
                bl[ntp * 2 + 1][0] = r4[2]; bl[ntp * 2 + 1][1] = r4[3];
            }
#pragma unroll
            for (int mt = 0; mt < 2; mt++)
#pragma unroll
                for (int ntf = 0; ntf < 8; ntf++) {
                    MMA16816(c[mt][ntf], ah[mt], bh[ntf]);
                    MMA16816(c[mt][ntf], ah[mt], bl[ntf]);
                    MMA16816(c[mt][ntf], al[mt], bh[ntf]);
                }
        }
    };

    LOAD(0); STORE(0);
    __syncthreads();
    for (int kc = 0; kc < 32; kc++) {
        int buf = kc & 1;
        if (kc < 31) LOAD(kc + 1);
        COMPUTE(buf);
        if (kc < 31) STORE(buf ^ 1);
        __syncthreads();
    }

    int qrow = lane >> 2, qcol = (lane & 3) * 2;
#pragma unroll
    for (int mt = 0; mt < 2; mt++) {
#pragma unroll
        for (int ntf = 0; ntf < 8; ntf++) {
            int n = n0 + wn * 64 + ntf * 8 + qcol;
            float2 bb = *(const float2*)&g_bP1[d][n];
            int r1 = wm * 32 + mt * 16 + qrow;
            int r2 = r1 + 8;
            *(float2*)&g_Z[d][t][r1][n] =
                make_float2(c[mt][ntf][0] + bb.x, c[mt][ntf][1] + bb.y);
            *(float2*)&g_Z[d][t][r2][n] =
                make_float2(c[mt][ntf][2] + bb.x, c[mt][ntf][3] + bb.y);
        }
    }
}

__device__ __forceinline__ void do_packst(int bid, int w, int pb) {
    for (int i = bid * 320 + threadIdx.x; i < Rd * 2 * Hd; i += NBLK * 320) {
        int r = i / (2 * Hd), k = i % (2 * Hd);
        int nc = r >> 5, b = r & 31;
        __nv_bfloat16 hv, lv;
        if (k < Hd) { hv = g_hbH[pb][1][1][r][k]; lv = g_hbL[pb][1][1][r][k]; }
        else        { hv = g_hbH[pb][1][0][r][k - Hd]; lv = g_hbL[pb][1][0][r][k - Hd]; }
        int m = (nc * Td + w) * Bd + b;
        g_packedH[m][k] = hv;
        g_packedL[m][k] = lv;
    }
}

// =========================================================================
// persistent chain: whole recurrent schedule in ONE launch (128 blocks)
// =========================================================================
__global__ void __launch_bounds__(320, 1) k_chain() {
    extern __shared__ __align__(16) char dsm[];
    int bid = blockIdx.x;
    int z = bid >> 5, lay_b = z >> 1, d_b = z & 1;
    int n0_b = (bid & 31) * 64;
    int p0 = 0, p1 = 0;

    // prelude: layer0 word 0, step 0
    if (lay_b == 0) do_step(dsm, n0_b, 0, d_b, p0, 0, 0);
    p0 ^= 1;
    gbar();
    for (int tile = bid; tile < 32; tile += NBLK) {
        int t = tile >> 5, d = (tile >> 4) & 1, nt = tile & 15;
        do_zproj(dsm, t, d, nt, 0);
    }
    gbar();

    for (int w = 0; w < Td; w++) {
        int s0max = (w + 1 < Td) ? (w + 1) : -1;   // layer0 word w+1
        int s1max = w;                              // layer1 word w
        int smax = s0max > s1max ? s0max : s1max;
        for (int s = 0; s <= smax; s++) {
            int a0 = (s <= s0max) ? 1 : 0;
            int a1 = (s <= s1max) ? 1 : 0;
            int act = lay_b ? a1 : a0;
            if (act) {
                if (lay_b == 0) do_step(dsm, n0_b, 0, d_b, p0, s, w + 1);
                else            do_step(dsm, n0_b, 1, d_b, p1, s, w);
            }
            if (a0) p0 ^= 1;
            if (a1) p1 ^= 1;
            gbar();
        }
        do_packst(bid, w, p1);
        if (w + 1 < Td) {
            int ntiles = (w + 2) * 32;
            for (int tile = bid; tile < ntiles; tile += NBLK) {
                int t = tile >> 5, d = (tile >> 4) & 1, nt = tile & 15;
                do_zproj(dsm, t, d, nt, w + 1);
            }
        }
        gbar();
    }
}

// =========================================================================
// final vocab projection (bf16-split mma.sync): grid (25, 239)
// =========================================================================
__global__ void __launch_bounds__(256, 1)
k_mma(const float* __restrict__ bfc, float* __restrict__ out) {
    extern __shared__ __align__(16) char dsm[];
    __nv_bfloat16* sA_h = (__nv_bfloat16*)dsm;
    __nv_bfloat16* sA_l = sA_h + 2 * 128 * PITCH;
    __nv_bfloat16* sB_h = sA_l + 2 * 128 * PITCH;
    __nv_bfloat16* sB_l = sB_h + 2 * 128 * PITCH;
    uint32_t uAh = smem_u32(sA_h), uAl = smem_u32(sA_l);
    uint32_t uBh = smem_u32(sB_h), uBl = smem_u32(sB_l);

    int tid = threadIdx.x;
    int lane = tid & 31, wid = tid >> 5;
    int wm = wid >> 1, wn = wid & 1;
    int m0 = blockIdx.x * 128, n0 = blockIdx.y * 128;

    int sr = tid & 127, kh = tid >> 7;
    int k0 = kh * 16;

    int am = m0 + sr;
    const __nv_bfloat16* aH0 = &g_packedH[am][0];
    const __nv_bfloat16* aL0 = &g_packedL[am][0];

    int bnr = n0 + sr;
    bool bvalid = (bnr < Vd);
    long boff = (long)bnr * Kfc;

    float c[2][8][4];
#pragma unroll
    for (int mt = 0; mt < 2; mt++)
#pragma unroll
        for (int nt = 0; nt < 8; nt++)
#pragma unroll
            for (int q = 0; q < 4; q++) c[mt][nt][q] = 0.f;

    uint4 vA[4], vB[4];

    auto LOAD = [&](int kc) {
        int kb = kc * 32 + k0;
        vA[0] = *(const uint4*)(aH0 + kb);
        vA[1] = *(const uint4*)(aH0 + kb + 8);
        vA[2] = *(const uint4*)(aL0 + kb);
        vA[3] = *(const uint4*)(aL0 + kb + 8);
        if (bvalid) {
            vB[0] = *(const uint4*)(g_WfcH + boff + kb);
            vB[1] = *(const uint4*)(g_WfcH + boff + kb + 8);
            vB[2] = *(const uint4*)(g_WfcL + boff + kb);
            vB[3] = *(const uint4*)(g_WfcL + boff + kb + 8);
        } else {
            uint4 zz = make_uint4(0, 0, 0, 0);
            vB[0] = zz; vB[1] = zz; vB[2] = zz; vB[3] = zz;
        }
    };
    auto STORE = [&](int buf) {
        int base = buf * 128 * PITCH + sr * PITCH + k0;
        *(uint4*)&sA_h[base] = vA[0]; *(uint4*)&sA_h[base + 8] = vA[1];
        *(uint4*)&sA_l[base] = vA[2]; *(uint4*)&sA_l[base + 8] = vA[3];
        *(uint4*)&sB_h[base] = vB[0]; *(uint4*)&sB_h[base + 8] = vB[1];
        *(uint4*)&sB_l[base] = vB[2]; *(uint4*)&sB_l[base + 8] = vB[3];
    };
    auto COMPUTE = [&](int buf) {
        uint32_t bo = (uint32_t)buf * 128 * PITCH * 2;
#pragma unroll
        for (int k16 = 0; k16 < 2; k16++) {
            int ar = lane & 15;
            int acs = k16 * 16 + ((lane >> 4) << 3);
            uint32_t ah[2][4], al[2][4];
#pragma unroll
            for (int mt = 0; mt < 2; mt++) {
                uint32_t off = bo + (uint32_t)((wm * 32 + mt * 16 + ar) * PITCH + acs) * 2;
                LDSM4(ah[mt], uAh + off);
                LDSM4(al[mt], uAl + off);
            }
            int br = (lane & 7) + ((lane >> 4) << 3);
            int bcs = k16 * 16 + (((lane >> 3) & 1) << 3);
            uint32_t bh[8][2], bl[8][2];
#pragma unroll
            for (int ntp = 0; ntp < 4; ntp++) {
                uint32_t off = bo + (uint32_t)((wn * 64 + ntp * 16 + br) * PITCH + bcs) * 2;
                uint32_t r4[4];
                LDSM4(r4, uBh + off);
                bh[ntp * 2][0] = r4[0]; bh[ntp * 2][1] = r4[1];
                bh[ntp * 2 + 1][0] = r4[2]; bh[ntp * 2 + 1][1] = r4[3];
                LDSM4(r4, uBl + off);
                bl[ntp * 2][0] = r4[0]; bl[ntp * 2][1] = r4[1];
                bl[ntp * 2 + 1][0] = r4[2]; bl[ntp * 2 + 1][1] = r4[3];
            }
#pragma unroll
            for (int mt = 0; mt < 2; mt++)
#pragma unroll
                for (int nt = 0; nt < 8; nt++) {
                    MMA16816(c[mt][nt], ah[mt], bh[nt]);
                    MMA16816(c[mt][nt], ah[mt], bl[nt]);
                    MMA16816(c[mt][nt], al[mt], bh[nt]);
                }
        }
    };

    LOAD(0); STORE(0);
    __syncthreads();
    for (int kc = 0; kc < 32; kc++) {
        int buf = kc & 1;
        if (kc < 31) LOAD(kc + 1);
        COMPUTE(buf);
        if (kc < 31) STORE(buf ^ 1);
        __syncthreads();
    }

    int qrow = lane >> 2, qcol = (lane & 3) * 2;
#pragma unroll
    for (int mt = 0; mt < 2; mt++) {
#pragma unroll
        for (int nt = 0; nt < 8; nt++) {
            int n = n0 + wn * 64 + nt * 8 + qcol;
            int mA = m0 + wm * 32 + mt * 16 + qrow;
            if (n < Vd) {
                float2 bb = *(const float2*)&bfc[n];
                *(float2*)&out[(long)mA * Vd + n] =
                    make_float2(c[mt][nt][0] + bb.x, c[mt][nt][1] + bb.y);
                *(float2*)&out[(long)(mA + 8) * Vd + n] =
                    make_float2(c[mt][nt][2] + bb.x, c[mt][nt][3] + bb.y);
            }
        }
    }
}

// ---------------- host orchestration (6 graph nodes) ----------------
#define MMA_SMEM (8 * 128 * PITCH * 2)   // 81920 bytes

extern "C" void kernel_launch(void* const* d_in, const int* in_sizes, int n_in,
                              void* d_out, int out_size) {
    const float* img  = (const float*)d_in[0];
    const int*   cap  = (const int*)d_in[1];
    const float* emb  = (const float*)d_in[2];
    const float* Wh   = (const float*)d_in[3];
    const float* bh   = (const float*)d_in[4];
    const float* Wc   = (const float*)d_in[5];
    const float* bc   = (const float*)d_in[6];
    const float* Wih0 = (const float*)d_in[7];
    const float* Whh0 = (const float*)d_in[8];
    const float* bih0 = (const float*)d_in[9];
    const float* bhh0 = (const float*)d_in[10];
    const float* Wih1 = (const float*)d_in[11];
    const float* Whh1 = (const float*)d_in[12];
    const float* bih1 = (const float*)d_in[13];
    const float* bhh1 = (const float*)d_in[14];
    const float* Wfc  = (const float*)d_in[15];
    const float* bfc  = (const float*)d_in[16];
    float* out = (float*)d_out;

    cudaFuncSetAttribute(k_mma, cudaFuncAttributeMaxDynamicSharedMemorySize, MMA_SMEM);
    cudaFuncSetAttribute(k_chain, cudaFuncAttributeMaxDynamicSharedMemorySize, CHAIN_SMEM);

    k_pack<<<dim3(4000, 3), 256>>>(Wih0, bih0, bhh0, bih1, bhh1);
    k_packbf<<<dim3(122088, 3), 256>>>(Wfc, Wih1, Whh0, Whh1);
    k_init<<<(2 * Bd * Hd + 255) / 256, 256>>>(img, Wh, bh, Wc, bc);
    k_xproj<<<dim3(100, 16, 2), 256>>>(emb, cap);
    k_chain<<<NBLK, 320, CHAIN_SMEM>>>();
    k_mma<<<dim3(25, 239), 256, MMA_SMEM>>>(bfc, out);
}

// round 14
// speedup vs baseline: 1.1474x; 1.1474x over previous
#include <cuda_runtime.h>
#include <cuda_fp16.h>
#include <math.h>
#include <stdint.h>

// Problem constants
#define Hd   512
#define G4   2048      // 4*H
#define Ed   250
#define Bd   32
#define NCd  5
#define Td   20
#define Rd   160       // NC*B
#define Vd   30522
#define CNNd 2048
#define Md   3200      // NC*T*B
#define Kfc  1024      // 2*H
#define PITCH 40       // smem row pitch in fp16 elems (80B, bank-conflict-free)
#define NBLK 128       // persistent chain blocks (all co-resident)

// ---------------- device scratch (no allocations allowed) ----------------
__device__ float g_WihP0[2][Ed][G4];
__device__ float g_bP0[2][G4];
__device__ float g_bP1[2][G4];
__device__ float g_X0[2][Td][Rd][G4];        // layer0 input projections (+bias)
__device__ float g_Z[2][Td][Rd][G4];         // layer1 input projections (+bias)
__device__ float g_cS[2][2][Rd][Hd];         // [layer][dir][row][h]  fp32 cell state
// LSTM h state as fp16 hi/lo (exact to 2^-22), double buffered
__device__ __half g_hbH[2][2][2][Rd][Hd];
__device__ __half g_hbL[2][2][2][Rd][Hd];
// fp16 hi/lo split activations (A operands for mma GEMMs)
__device__ __half g_hsH[2][Td][Rd][Hd];
__device__ __half g_hsL[2][Td][Rd][Hd];
__device__ __half g_packedH[Md][Kfc];
__device__ __half g_packedL[Md][Kfc];
// single-fp16 weights (B operands, K-major rows) — 2-term scheme
__device__ __half g_WfcH[(long)Vd * Kfc];
__device__ __half g_W1H[2L * G4 * Kfc];          // gate-interleaved [d][n][k]
__device__ __half g_WsH[2][2][G4][Hd];           // recurrent weights [lay][d][n][k]
// software grid barrier state (replay-safe: cnt returns to 0, gen monotonic)
__device__ unsigned g_bar_cnt = 0;
__device__ unsigned g_bar_gen = 0;

__device__ __forceinline__ uint32_t smem_u32(const void* p) {
    uint32_t a;
    asm("{ .reg .u64 t; cvta.to.shared.u64 t, %1; cvt.u32.u64 %0, t; }"
        : "=r"(a) : "l"(p));
    return a;
}
#define LDSM4(r, addr) \
    asm volatile("ldmatrix.sync.aligned.m8n8.x4.shared.b16 {%0,%1,%2,%3}, [%4];" \
        : "=r"((r)[0]), "=r"((r)[1]), "=r"((r)[2]), "=r"((r)[3]) : "r"(addr))
#define MMA16816(c, a, b) \
    asm volatile("mma.sync.aligned.m16n8k16.row.col.f32.f16.f16.f32 " \
        "{%0,%1,%2,%3}, {%4,%5,%6,%7}, {%8,%9}, {%0,%1,%2,%3};" \
        : "+f"((c)[0]), "+f"((c)[1]), "+f"((c)[2]), "+f"((c)[3]) \
        : "r"((a)[0]), "r"((a)[1]), "r"((a)[2]), "r"((a)[3]), "r"((b)[0]), "r"((b)[1]))

// ---- FFMA-only activations (kept from R13; rel err ~1.5e-7) ----
__device__ __forceinline__ float fsig(float x) {
    float u = fminf(fmaxf(-1.4426950408889634f * x, -80.f), 80.f);
    int e = __float2int_rn(u);
    float f = u - (float)e;
    float p = fmaf(1.5403530e-4f, f, 1.3333558e-3f);
    p = fmaf(p, f, 9.6181291e-3f);
    p = fmaf(p, f, 5.5504109e-2f);
    p = fmaf(p, f, 2.4022651e-1f);
    p = fmaf(p, f, 6.9314718e-1f);
    p = fmaf(p, f, 1.0f);
    float s = __int_as_float((e + 127) << 23);
    float den = fmaf(p, s, 1.0f);
    float r = __int_as_float(0x7EF311C3 - __float_as_int(den));
    r = r * fmaf(-den, r, 2.0f);
    r = r * fmaf(-den, r, 2.0f);
    r = r * fmaf(-den, r, 2.0f);
    return r;
}
__device__ __forceinline__ float ftanh(float x) {
    return fmaf(2.0f, fsig(2.0f * x), -1.0f);
}

// ---- grid barrier (all NBLK blocks must be resident) ----
__device__ __forceinline__ void gbar() {
    __syncthreads();
    if (threadIdx.x == 0) {
        __threadfence();
        unsigned gen = atomicAdd(&g_bar_gen, 0u);
        if (atomicAdd(&g_bar_cnt, 1u) == NBLK - 1) {
            atomicExch(&g_bar_cnt, 0u);
            __threadfence();
            atomicAdd(&g_bar_gen, 1u);
        } else {
            while (atomicAdd(&g_bar_gen, 0u) == gen) __nanosleep(64);
        }
        __threadfence();
    }
    __syncthreads();
}

// ---------------- weight packing (fp32 for xproj, biases) ----------------
__global__ void k_pack(const float* __restrict__ Wih0,
                       const float* __restrict__ bih0, const float* __restrict__ bhh0,
                       const float* __restrict__ bih1, const float* __restrict__ bhh1) {
    int region = blockIdx.y;
    long i = (long)blockIdx.x * blockDim.x + threadIdx.x;
    if (region == 0) {
        if (i >= 2L * Ed * G4) return;
        int d = (int)(i / (Ed * G4)); int rem = (int)(i % (Ed * G4));
        int k = rem / G4, n = rem % G4;
        int h = n >> 2, g = n & 3;
        g_WihP0[d][k][n] = Wih0[((long)d * G4 + g * Hd + h) * Ed + k];
    } else if (region == 1) {
        if (i >= 2L * G4) return;
        int d = (int)(i / G4); int n = (int)(i % G4);
        int h = n >> 2, g = n & 3;
        long j = (long)d * G4 + g * Hd + h;
        g_bP0[d][n] = bih0[j] + bhh0[j];
    } else {
        if (i >= 2L * G4) return;
        int d = (int)(i / G4); int n = (int)(i % G4);
        int h = n >> 2, g = n & 3;
        long j = (long)d * G4 + g * Hd + h;
        g_bP1[d][n] = bih1[j] + bhh1[j];
    }
}

// ---------------- fp16 weight packing (single, gate-interleaved) ----------------
__global__ void k_packbf(const float* __restrict__ Wfc, const float* __restrict__ Wih1,
                         const float* __restrict__ Whh0, const float* __restrict__ Whh1) {
    long i = (long)blockIdx.x * blockDim.x + threadIdx.x;
    if (blockIdx.y == 0) {
        if (i >= (long)Vd * Kfc) return;
        g_WfcH[i] = __float2half(Wfc[i]);
    } else if (blockIdx.y == 1) {
        if (i >= 2L * G4 * Kfc) return;
        int d = (int)(i / (G4 * Kfc)); long rem = i % ((long)G4 * Kfc);
        int n = (int)(rem / Kfc), k = (int)(rem % Kfc);
        int h = n >> 2, g = n & 3;
        g_W1H[i] = __float2half(Wih1[((long)d * G4 + g * Hd + h) * Kfc + k]);
    } else {
        if (i >= 2L * 2 * G4 * Hd) return;
        int lay = (int)(i / (2L * G4 * Hd));
        long rem = i % (2L * G4 * Hd);
        int d = (int)(rem / ((long)G4 * Hd));
        long r2 = rem % ((long)G4 * Hd);
        int n = (int)(r2 / Hd), k = (int)(r2 % Hd);
        int h = n >> 2, g = n & 3;
        const float* W = lay ? Whh1 : Whh0;
        g_WsH[lay][d][n][k] = __float2half(W[((long)d * G4 + g * Hd + h) * Hd + k]);
    }
}

// ---------------- initial states: fp16 hi/lo h0, fp32 c0 ----------------
__global__ void k_init(const float* __restrict__ img, const float* __restrict__ Wh,
                       const float* __restrict__ bh, const float* __restrict__ Wc,
                       const float* __restrict__ bc) {
    int i = blockIdx.x * blockDim.x + threadIdx.x;
    if (i >= 2 * Bd * Hd) return;
    int which = i / (Bd * Hd);
    int rem = i % (Bd * Hd);
    int b = rem / Hd, j = rem % Hd;
    const float* W = which ? Wc : Wh;
    const float* bias = which ? bc : bh;
    const float4* a4 = (const float4*)(img + (long)b * CNNd);
    const float4* w4 = (const float4*)(W + (long)j * CNNd);
    float acc = 0.f;
#pragma unroll 4
    for (int k = 0; k < CNNd / 4; k++) {
        float4 a = a4[k], w = w4[k];
        acc += a.x * w.x + a.y * w.y + a.z * w.z + a.w * w.w;
    }
    float v = fmaxf(acc + bias[j], 0.f);
    __half hv = __float2half(v);
    __half lv = __float2half(v - __half2float(hv));
    for (int nc = 0; nc < NCd; nc++) {
        int row = nc * Bd + b;
        for (int l = 0; l < 2; l++)
            for (int d = 0; d < 2; d++) {
                if (which == 0) { g_hbH[0][l][d][row][j] = hv; g_hbL[0][l][d][row][j] = lv; }
                else            g_cS[l][d][row][j] = v;
            }
    }
}

// ---------------- layer0 input projections for all t (fp32 FFMA) ----------------
__global__ void k_xproj(const float* __restrict__ emb, const int* __restrict__ cap) {
    __shared__ float xs[32 * Ed];
    __shared__ int toks[32];
    int bm = blockIdx.x, bn = blockIdx.y, d = blockIdx.z;
    int tid = threadIdx.x;
    if (tid < 32) {
        int m = bm * 32 + tid;
        int t = m / Rd, r = m % Rd;
        int nc = r >> 5, b = r & 31;
        toks[tid] = cap[b * (NCd * Td) + nc * Td + t];
    }
    __syncthreads();
    for (int e = tid; e < 32 * Ed; e += 256) {
        int lr = e / Ed, k = e % Ed;
        xs[e] = emb[(long)toks[lr] * Ed + k];
    }
    __syncthreads();
    int tx = tid & 31, ty = tid >> 5;
    float acc[4][4];
#pragma unroll
    for (int a = 0; a < 4; a++)
#pragma unroll
        for (int c = 0; c < 4; c++) acc[a][c] = 0.f;
    int n0 = bn * 128;
    const float* Bp = &g_WihP0[d][0][0];
#pragma unroll 5
    for (int k = 0; k < Ed; k++) {
        float av[4], bv[4];
#pragma unroll
        for (int jr = 0; jr < 4; jr++) av[jr] = xs[(ty + jr * 8) * Ed + k];
#pragma unroll
        for (int jc = 0; jc < 4; jc++) bv[jc] = Bp[(long)k * G4 + n0 + tx + jc * 32];
#pragma unroll
        for (int jr = 0; jr < 4; jr++)
#pragma unroll
            for (int jc = 0; jc < 4; jc++) acc[jr][jc] += av[jr] * bv[jc];
    }
    int m0 = bm * 32;
#pragma unroll
    for (int jr = 0; jr < 4; jr++) {
        int m = m0 + ty + jr * 8;
        int t = m / Rd, r = m % Rd;
#pragma unroll
        for (int jc = 0; jc < 4; jc++) {
            int n = n0 + tx + jc * 32;
            g_X0[d][t][r][n] = acc[jr][jc] + g_bP0[d][n];
        }
    }
}

// =========================================================================
// chain smem: A hi/lo double-buffered + B single-precision double-buffered
// =========================================================================
#define A_ELEMS (2 * 160 * PITCH)      // halves, per A array (double-buffered)
#define B_ELEMS (2 * 128 * PITCH)      // halves (double-buffered)
#define CHAIN_SMEM ((2 * A_ELEMS + B_ELEMS) * 2)

// ---- one recurrent LSTM step tile: block tile 160x64, warp 32x32 (5m x 2n) ----
// gates = X + h @ Whh^T; 2-term fp16: Ah*B + Al*B (B = single fp16 weights)
__device__ __forceinline__ void do_step(char* dsm, int n0, int lay, int d,
                                        int p, int s, int w) {
    __half* sA_h = (__half*)dsm;
    __half* sA_l = sA_h + A_ELEMS;
    __half* sB_h = sA_l + A_ELEMS;
    uint32_t uAh = smem_u32(sA_h), uAl = smem_u32(sA_l);
    uint32_t uBh = smem_u32(sB_h);

    int tid = threadIdx.x;
    int lane = tid & 31, wid = tid >> 5;
    int wm = wid >> 1, wn = wid & 1;

    const __half* hH = &g_hbH[p][lay][d][0][0];
    const __half* hL = &g_hbL[p][lay][d][0][0];
    __half* hoH = &g_hbH[p ^ 1][lay][d][0][0];
    __half* hoL = &g_hbL[p ^ 1][lay][d][0][0];
    float* cstp = &g_cS[lay][d][0][0];
    int xidx = d ? (w - s) : s;
    const float* Xp = lay ? &g_Z[d][xidx][0][0] : &g_X0[d][xidx][0][0];
    const __half* BH = &g_WsH[lay][d][0][0];

    int arow = (tid >= 160) ? tid - 160 : tid;
    int ak0 = (tid >= 160) ? 16 : 0;
    int brow = tid >> 1, bk0 = (tid & 1) * 16;

    float c[2][4][4];
#pragma unroll
    for (int mt = 0; mt < 2; mt++)
#pragma unroll
        for (int nt = 0; nt < 4; nt++)
#pragma unroll
            for (int q = 0; q < 4; q++) c[mt][nt][q] = 0.f;

    uint4 vA[4], vB[2];

    auto LOAD = [&](int kc) {
        int ka = kc * 32 + ak0;
        vA[0] = *(const uint4*)(hH + arow * Hd + ka);
        vA[1] = *(const uint4*)(hH + arow * Hd + ka + 8);
        vA[2] = *(const uint4*)(hL + arow * Hd + ka);
        vA[3] = *(const uint4*)(hL + arow * Hd + ka + 8);
        if (tid < 128) {
            long bo = (long)(n0 + brow) * Hd + kc * 32 + bk0;
            vB[0] = *(const uint4*)(BH + bo);
            vB[1] = *(const uint4*)(BH + bo + 8);
        }
    };
    auto STORE = [&](int buf) {
        int sa = buf * 160 * PITCH + arow * PITCH + ak0;
        *(uint4*)&sA_h[sa] = vA[0]; *(uint4*)&sA_h[sa + 8] = vA[1];
        *(uint4*)&sA_l[sa] = vA[2]; *(uint4*)&sA_l[sa + 8] = vA[3];
        if (tid < 128) {
            int sbb = buf * 64 * PITCH + brow * PITCH + bk0;
            *(uint4*)&sB_h[sbb] = vB[0]; *(uint4*)&sB_h[sbb + 8] = vB[1];
        }
    };
    auto COMPUTE = [&](int buf) {
        uint32_t boA = (uint32_t)buf * 160 * PITCH * 2;
        uint32_t boB = (uint32_t)buf * 64 * PITCH * 2;
#pragma unroll
        for (int k16 = 0; k16 < 2; k16++) {
            int ar = lane & 15;
            int acs = k16 * 16 + ((lane >> 4) << 3);
            uint32_t ah[2][4], al[2][4];
#pragma unroll
            for (int mt = 0; mt < 2; mt++) {
                uint32_t off = boA + (uint32_t)((wm * 32 + mt * 16 + ar) * PITCH + acs) * 2;
                LDSM4(ah[mt], uAh + off);
                LDSM4(al[mt], uAl + off);
            }
            int br = (lane & 7) + ((lane >> 4) << 3);
            int bcs = k16 * 16 + (((lane >> 3) & 1) << 3);
            uint32_t bh[4][2];
#pragma unroll
            for (int ntp = 0; ntp < 2; ntp++) {
                uint32_t off = boB + (uint32_t)((wn * 32 + ntp * 16 + br) * PITCH + bcs) * 2;
                uint32_t r4[4];
                LDSM4(r4, uBh + off);
                bh[ntp * 2][0] = r4[0]; bh[ntp * 2][1] = r4[1];
                bh[ntp * 2 + 1][0] = r4[2]; bh[ntp * 2 + 1][1] = r4[3];
            }
#pragma unroll
            for (int mt = 0; mt < 2; mt++)
#pragma unroll
                for (int nt = 0; nt < 4; nt++) {
                    MMA16816(c[mt][nt], ah[mt], bh[nt]);
                    MMA16816(c[mt][nt], al[mt], bh[nt]);
                }
        }
    };

    LOAD(0); STORE(0);
    __syncthreads();
    for (int kc = 0; kc < 16; kc++) {
        int buf = kc & 1;
        if (kc < 15) LOAD(kc + 1);
        COMPUTE(buf);
        if (kc < 15) STORE(buf ^ 1);
        __syncthreads();
    }

    // ---- fused LSTM cell epilogue: FFMA-only activations, ALL lanes active ----
    int qrow = lane >> 2, quad = lane & 3;
    bool isIF = (quad & 1) == 0;
#pragma unroll
    for (int mt = 0; mt < 2; mt++) {
#pragma unroll
        for (int nt = 0; nt < 4; nt++) {
            int nbase = n0 + wn * 32 + nt * 8;
            int n = nbase + quad * 2;
            int r1 = wm * 32 + mt * 16 + qrow;
            int r2 = r1 + 8;
            float2 x1 = *(const float2*)&Xp[(long)r1 * G4 + n];
            float2 x2 = *(const float2*)&Xp[(long)r2 * G4 + n];
            float a0 = c[mt][nt][0] + x1.x;
            float a1 = c[mt][nt][1] + x1.y;
            float a2 = c[mt][nt][2] + x2.x;
            float a3 = c[mt][nt][3] + x2.y;
            float b0 = __shfl_xor_sync(0xffffffffu, a0, 1);
            float b1 = __shfl_xor_sync(0xffffffffu, a1, 1);
            float b2 = __shfl_xor_sync(0xffffffffu, a2, 1);
            float b3 = __shfl_xor_sync(0xffffffffu, a3, 1);
            int hh = (nbase >> 2) + (quad >> 1);
            int row = isIF ? r1 : r2;
            float gi = isIF ? a0 : b2;
            float gf = isIF ? a1 : b3;
            float gg = isIF ? b0 : a2;
            float go = isIF ? b1 : a3;
            float si = fsig(gi);
            float sf = fsig(gf);
            float so = fsig(go);
            float tg = ftanh(gg);
            float cc = fmaf(sf, cstp[row * Hd + hh], si * tg);
            float h = so * ftanh(cc);
            cstp[row * Hd + hh] = cc;
            __half hb = __float2half(h);
            __half lb = __float2half(h - __half2float(hb));
            hoH[row * Hd + hh] = hb;
            hoL[row * Hd + hh] = lb;
            if (lay == 0) {
                g_hsH[d][s][row][hh] = hb;
                g_hsL[d][s][row][hh] = lb;
            }
        }
    }
}

// ---- one zproj tile: 160x128, warp tile 32x64 (5m x 2n), K=1024, 2-term ----
__device__ __forceinline__ void do_zproj(char* dsm, int t, int d, int nt, int w) {
    __half* sA_h = (__half*)dsm;
    __half* sA_l = sA_h + A_ELEMS;
    __half* sB_h = sA_l + A_ELEMS;
    uint32_t uAh = smem_u32(sA_h), uAl = smem_u32(sA_l);
    uint32_t uBh = smem_u32(sB_h);

    int tid = threadIdx.x;
    int lane = tid & 31, wid = tid >> 5;
    int wm = wid >> 1, wn = wid & 1;
    int n0 = nt * 128;
    int tb = w - t;

    int arow = (tid >= 160) ? tid - 160 : tid;
    int ak0 = (tid >= 160) ? 16 : 0;
    int brow = tid >> 1, bk0 = (tid & 1) * 16;   // tid < 256

    float c[2][8][4];
#pragma unroll
    for (int mt = 0; mt < 2; mt++)
#pragma unroll
        for (int ntf = 0; ntf < 8; ntf++)
#pragma unroll
            for (int q = 0; q < 4; q++) c[mt][ntf][q] = 0.f;

    uint4 vA[4], vB[2];

    auto LOAD = [&](int kc) {
        int ka = kc * 32 + ak0;
        const __half* pH = (ka < Hd) ? &g_hsH[0][t][arow][ka]
                                     : &g_hsH[1][tb][arow][ka - Hd];
        const __half* pL = (ka < Hd) ? &g_hsL[0][t][arow][ka]
                                     : &g_hsL[1][tb][arow][ka - Hd];
        vA[0] = *(const uint4*)pH;
        vA[1] = *(const uint4*)(pH + 8);
        vA[2] = *(const uint4*)pL;
        vA[3] = *(const uint4*)(pL + 8);
        if (tid < 256) {
            long bo = ((long)d * G4 + n0 + brow) * Kfc + kc * 32 + bk0;
            vB[0] = *(const uint4*)(g_W1H + bo);
            vB[1] = *(const uint4*)(g_W1H + bo + 8);
        }
    };
    auto STORE = [&](int buf) {
        int sa = buf * 160 * PITCH + arow * PITCH + ak0;
        *(uint4*)&sA_h[sa] = vA[0]; *(uint4*)&sA_h[sa + 8] = vA[1];
        *(uint4*)&sA_l[sa] = vA[2]; *(uint4*)&sA_l[sa + 8] = vA[3];
        if (tid < 256) {
            int sbb = buf * 128 * PITCH + brow * PITCH + bk0;
            *(uint4*)&sB_h[sbb] = vB[0]; *(uint4*)&sB_h[sbb + 8] = vB[1];
        }
    };
    auto COMPUTE = [&](int buf) {
        uint32_t boA = (uint32_t)buf * 160 * PITCH * 2;
        uint32_t boB = (uint32_t)buf * 128 * PITCH * 2;
#pragma unroll
        for (int k16 = 0; k16 < 2; k16++) {
            int ar = lane & 15;
            int acs = k16 * 16 + ((lane >> 4) << 3);
            uint32_t ah[2][4], al[2][4];
#pragma unroll
            for (int mt = 0; mt < 2; mt++) {
                uint32_t off = boA + (uint32_t)((wm * 32 + mt * 16 + ar) * PITCH + acs) * 2;
                LDSM4(ah[mt], uAh + off);
                LDSM4(al[mt], uAl + off);
            }
            int br = (lane & 7) + ((lane >> 4) << 3);
            int bcs = k16 * 16 + (((lane >> 3) & 1) << 3);
            uint32_t bh[8][2];
#pragma unroll
            for (int ntp = 0; ntp < 4; ntp++) {
                uint32_t off = boB + (uint32_t)((wn * 64 + ntp * 16 + br) * PITCH + bcs) * 2;
                uint32_t r4[4];
                LDSM4(r4, uBh + off);
                bh[ntp * 2][0] = r4[0]; bh[ntp * 2][1] = r4[1];
                bh[ntp * 2 + 1][0] = r4[2]; bh[ntp * 2 + 1][1] = r4[3];
            }
#pragma unroll
            for (int mt = 0; mt < 2; mt++)
#pragma unroll
                for (int ntf = 0; ntf < 8; ntf++) {
                    MMA16816(c[mt][ntf], ah[mt], bh[ntf]);
                    MMA16816(c[mt][ntf], al[mt], bh[ntf]);
                }
        }
    };

    LOAD(0); STORE(0);
    __syncthreads();
    for (int kc = 0; kc < 32; kc++) {
        int buf = kc & 1;
        if (kc < 31) LOAD(kc + 1);
        COMPUTE(buf);
        if (kc < 31) STORE(buf ^ 1);
        __syncthreads();
    }

    int qrow = lane >> 2, qcol = (lane & 3) * 2;
#pragma unroll
    for (int mt = 0; mt < 2; mt++) {
#pragma unroll
        for (int ntf = 0; ntf < 8; ntf++) {
            int n = n0 + wn * 64 + ntf * 8 + qcol;
            float2 bb = *(const float2*)&g_bP1[d][n];
            int r1 = wm * 32 + mt * 16 + qrow;
            int r2 = r1 + 8;
            *(float2*)&g_Z[d][t][r1][n] =
                make_float2(c[mt][ntf][0] + bb.x, c[mt][ntf][1] + bb.y);
            *(float2*)&g_Z[d][t][r2][n] =
                make_float2(c[mt][ntf][2] + bb.x, c[mt][ntf][3] + bb.y);
        }
    }
}

__device__ __forceinline__ void do_packst(int bid, int w, int pb) {
    for (int i = bid * 320 + threadIdx.x; i < Rd * 2 * Hd; i += NBLK * 320) {
        int r = i / (2 * Hd), k = i % (2 * Hd);
        int nc = r >> 5, b = r & 31;
        __half hv, lv;
        if (k < Hd) { hv = g_hbH[pb][1][1][r][k]; lv = g_hbL[pb][1][1][r][k]; }
        else        { hv = g_hbH[pb][1][0][r][k - Hd]; lv = g_hbL[pb][1][0][r][k - Hd]; }
        int m = (nc * Td + w) * Bd + b;
        g_packedH[m][k] = hv;
        g_packedL[m][k] = lv;
    }
}

// =========================================================================
// persistent chain: whole recurrent schedule in ONE launch (128 blocks)
// =========================================================================
__global__ void __launch_bounds__(320, 1) k_chain() {
    extern __shared__ __align__(16) char dsm[];
    int bid = blockIdx.x;
    int z = bid >> 5, lay_b = z >> 1, d_b = z & 1;
    int n0_b = (bid & 31) * 64;
    int p0 = 0, p1 = 0;

    if (lay_b == 0) do_step(dsm, n0_b, 0, d_b, p0, 0, 0);
    p0 ^= 1;
    gbar();
    for (int tile = bid; tile < 32; tile += NBLK) {
        int t = tile >> 5, d = (tile >> 4) & 1, nt = tile & 15;
        do_zproj(dsm, t, d, nt, 0);
    }
    gbar();

    for (int w = 0; w < Td; w++) {
        int s0max = (w + 1 < Td) ? (w + 1) : -1;   // layer0 word w+1
        int s1max = w;                              // layer1 word w
        int smax = s0max > s1max ? s0max : s1max;
        for (int s = 0; s <= smax; s++) {
            int a0 = (s <= s0max) ? 1 : 0;
            int a1 = (s <= s1max) ? 1 : 0;
            int act = lay_b ? a1 : a0;
            if (act) {
                if (lay_b == 0) do_step(dsm, n0_b, 0, d_b, p0, s, w + 1);
                else            do_step(dsm, n0_b, 1, d_b, p1, s, w);
            }
            if (a0) p0 ^= 1;
            if (a1) p1 ^= 1;
            gbar();
        }
        do_packst(bid, w, p1);
        if (w + 1 < Td) {
            int ntiles = (w + 2) * 32;
            for (int tile = bid; tile < ntiles; tile += NBLK) {
                int t = tile >> 5, d = (tile >> 4) & 1, nt = tile & 15;
                do_zproj(dsm, t, d, nt, w + 1);
            }
        }
        gbar();
    }
}

// =========================================================================
// final vocab projection (2-term fp16 mma.sync): grid (25, 239)
// =========================================================================
#define FB_ELEMS (2 * 128 * PITCH)
__global__ void __launch_bounds__(256)
k_mma(const float* __restrict__ bfc, float* __restrict__ out) {
    extern __shared__ __align__(16) char dsm[];
    __half* sA_h = (__half*)dsm;
    __half* sA_l = sA_h + FB_ELEMS;
    __half* sB_h = sA_l + FB_ELEMS;
    uint32_t uAh = smem_u32(sA_h), uAl = smem_u32(sA_l);
    uint32_t uBh = smem_u32(sB_h);

    int tid = threadIdx.x;
    int lane = tid & 31, wid = tid >> 5;
    int wm = wid >> 1, wn = wid & 1;
    int m0 = blockIdx.x * 128, n0 = blockIdx.y * 128;

    int sr = tid & 127, kh = tid >> 7;
    int k0 = kh * 16;

    int am = m0 + sr;
    const __half* aH0 = &g_packedH[am][0];
    const __half* aL0 = &g_packedL[am][0];

    int bnr = n0 + sr;
    bool bvalid = (bnr < Vd);
    long boff = (long)bnr * Kfc;

    float c[2][8][4];
#pragma unroll
    for (int mt = 0; mt < 2; mt++)
#pragma unroll
        for (int nt = 0; nt < 8; nt++)
#pragma unroll
            for (int q = 0; q < 4; q++) c[mt][nt][q] = 0.f;

    uint4 vA[4], vB[2];

    auto LOAD = [&](int kc) {
        int kb = kc * 32 + k0;
        vA[0] = *(const uint4*)(aH0 + kb);
        vA[1] = *(const uint4*)(aH0 + kb + 8);
        vA[2] = *(const uint4*)(aL0 + kb);
        vA[3] = *(const uint4*)(aL0 + kb + 8);
        if (bvalid) {
            vB[0] = *(const uint4*)(g_WfcH + boff + kb);
            vB[1] = *(const uint4*)(g_WfcH + boff + kb + 8);
        } else {
            uint4 zz = make_uint4(0, 0, 0, 0);
            vB[0] = zz; vB[1] = zz;
        }
    };
    auto STORE = [&](int buf) {
        int base = buf * 128 * PITCH + sr * PITCH + k0;
        *(uint4*)&sA_h[base] = vA[0]; *(uint4*)&sA_h[base + 8] = vA[1];
        *(uint4*)&sA_l[base] = vA[2]; *(uint4*)&sA_l[base + 8] = vA[3];
        *(uint4*)&sB_h[base] = vB[0]; *(uint4*)&sB_h[base + 8] = vB[1];
    };
    auto COMPUTE = [&](int buf) {
        uint32_t bo = (uint32_t)buf * 128 * PITCH * 2;
#pragma unroll
        for (int k16 = 0; k16 < 2; k16++) {
            int ar = lane & 15;
            int acs = k16 * 16 + ((lane >> 4) << 3);
            uint32_t ah[2][4], al[2][4];
#pragma unroll
            for (int mt = 0; mt < 2; mt++) {
                uint32_t off = bo + (uint32_t)((wm * 32 + mt * 16 + ar) * PITCH + acs) * 2;
                LDSM4(ah[mt], uAh + off);
                LDSM4(al[mt], uAl + off);
            }
            int br = (lane & 7) + ((lane >> 4) << 3);
            int bcs = k16 * 16 + (((lane >> 3) & 1) << 3);
            uint32_t bh[8][2];
#pragma unroll
            for (int ntp = 0; ntp < 4; ntp++) {
                uint32_t off = bo + (uint32_t)((wn * 64 + ntp * 16 + br) * PITCH + bcs) * 2;
                uint32_t r4[4];
                LDSM4(r4, uBh + off);
                bh[ntp * 2][0] = r4[0]; bh[ntp * 2][1] = r4[1];
                bh[ntp * 2 + 1][0] = r4[2]; bh[ntp * 2 + 1][1] = r4[3];
            }
#pragma unroll
            for (int mt = 0; mt < 2; mt++)
#pragma unroll
                for (int nt = 0; nt < 8; nt++) {
                    MMA16816(c[mt][nt], ah[mt], bh[nt]);
                    MMA16816(c[mt][nt], al[mt], bh[nt]);
                }
        }
    };

    LOAD(0); STORE(0);
    __syncthreads();
    for (int kc = 0; kc < 32; kc++) {
        int buf = kc & 1;
        if (kc < 31) LOAD(kc + 1);
        COMPUTE(buf);
        if (kc < 31) STORE(buf ^ 1);
        __syncthreads();
    }

    int qrow = lane >> 2, qcol = (lane & 3) * 2;
#pragma unroll
    for (int mt = 0; mt < 2; mt++) {
#pragma unroll
        for (int nt = 0; nt < 8; nt++) {
            int n = n0 + wn * 64 + nt * 8 + qcol;
            int mA = m0 + wm * 32 + mt * 16 + qrow;
            if (n < Vd) {
                float2 bb = *(const float2*)&bfc[n];
                *(float2*)&out[(long)mA * Vd + n] =
                    make_float2(c[mt][nt][0] + bb.x, c[mt][nt][1] + bb.y);
                *(float2*)&out[(long)(mA + 8) * Vd + n] =
                    make_float2(c[mt][nt][2] + bb.x, c[mt][nt][3] + bb.y);
            }
        }
    }
}

// ---------------- host orchestration (6 graph nodes) ----------------
#define MMA_SMEM (3 * FB_ELEMS * 2)   // 61440 bytes

extern "C" void kernel_launch(void* const* d_in, const int* in_sizes, int n_in,
                              void* d_out, int out_size) {
    const float* img  = (const float*)d_in[0];
    const int*   cap  = (const int*)d_in[1];
    const float* emb  = (const float*)d_in[2];
    const float* Wh   = (const float*)d_in[3];
    const float* bh   = (const float*)d_in[4];
    const float* Wc   = (const float*)d_in[5];
    const float* bc   = (const float*)d_in[6];
    const float* Wih0 = (const float*)d_in[7];
    const float* Whh0 = (const float*)d_in[8];
    const float* bih0 = (const float*)d_in[9];
    const float* bhh0 = (const float*)d_in[10];
    const float* Wih1 = (const float*)d_in[11];
    const float* Whh1 = (const float*)d_in[12];
    const float* bih1 = (const float*)d_in[13];
    const float* bhh1 = (const float*)d_in[14];
    const float* Wfc  = (const float*)d_in[15];
    const float* bfc  = (const float*)d_in[16];
    float* out = (float*)d_out;

    cudaFuncSetAttribute(k_mma, cudaFuncAttributeMaxDynamicSharedMemorySize, MMA_SMEM);
    cudaFuncSetAttribute(k_chain, cudaFuncAttributeMaxDynamicSharedMemorySize, CHAIN_SMEM);

    k_pack<<<dim3(4000, 3), 256>>>(Wih0, bih0, bhh0, bih1, bhh1);
    k_packbf<<<dim3(122088, 3), 256>>>(Wfc, Wih1, Whh0, Whh1);
    k_init<<<(2 * Bd * Hd + 255) / 256, 256>>>(img, Wh, bh, Wc, bc);
    k_xproj<<<dim3(100, 16, 2), 256>>>(emb, cap);
    k_chain<<<NBLK, 320, CHAIN_SMEM>>>();
    k_mma<<<dim3(25, 239), 256, MMA_SMEM>>>(bfc, out);
}

// round 15
// speedup vs baseline: 1.6011x; 1.3954x over previous
#include <cuda_runtime.h>
#include <cuda_fp16.h>
#include <math.h>
#include <stdint.h>

// Problem constants
#define Hd   512
#define G4   2048      // 4*H
#define Ed   250
#define Bd   32
#define NCd  5
#define Td   20
#define Rd   160       // NC*B
#define Vd   30522
#define CNNd 2048
#define Md   3200      // NC*T*B
#define Kfc  1024      // 2*H
#define PITCH 40       // smem row pitch in fp16 elems (80B, conflict-free, 16B-mult)
#define NBLK 128       // persistent chain blocks (all co-resident)
#define CTH  640       // chain block threads (20 warps = 5/SMSP, balanced)

// ---------------- device scratch (no allocations allowed) ----------------
__device__ float g_WihP0[2][Ed][G4];
__device__ float g_bP0[2][G4];
__device__ float g_bP1[2][G4];
__device__ float g_X0[2][Td][Rd][G4];
__device__ float g_Z[2][Td][Rd][G4];
__device__ float g_cS[2][2][Rd][Hd];
// LSTM h state as fp16 hi/lo (exact to 2^-22), double buffered
__device__ __half g_hbH[2][2][2][Rd][Hd];
__device__ __half g_hbL[2][2][2][Rd][Hd];
// fp16 hi/lo split activations
__device__ __half g_hsH[2][Td][Rd][Hd];
__device__ __half g_hsL[2][Td][Rd][Hd];
__device__ __half g_packedH[Md][Kfc];
__device__ __half g_packedL[Md][Kfc];
// single-fp16 weights (B operands, K-major rows)
__device__ __half g_WfcH[(long)Vd * Kfc];
__device__ __half g_W1H[2L * G4 * Kfc];
__device__ __half g_WsH[2][2][G4][Hd];
// grid barrier state
__device__ unsigned g_bar_cnt = 0;
__device__ unsigned g_bar_gen = 0;

__device__ __forceinline__ uint32_t smem_u32(const void* p) {
    uint32_t a;
    asm("{ .reg .u64 t; cvta.to.shared.u64 t, %1; cvt.u32.u64 %0, t; }"
        : "=r"(a) : "l"(p));
    return a;
}
#define LDSM4(r, addr) \
    asm volatile("ldmatrix.sync.aligned.m8n8.x4.shared.b16 {%0,%1,%2,%3}, [%4];" \
        : "=r"((r)[0]), "=r"((r)[1]), "=r"((r)[2]), "=r"((r)[3]) : "r"(addr))
#define MMA16816(c, a, b) \
    asm volatile("mma.sync.aligned.m16n8k16.row.col.f32.f16.f16.f32 " \
        "{%0,%1,%2,%3}, {%4,%5,%6,%7}, {%8,%9}, {%0,%1,%2,%3};" \
        : "+f"((c)[0]), "+f"((c)[1]), "+f"((c)[2]), "+f"((c)[3]) \
        : "r"((a)[0]), "r"((a)[1]), "r"((a)[2]), "r"((a)[3]), "r"((b)[0]), "r"((b)[1]))
#define CPA16(dst, src) \
    asm volatile("cp.async.cg.shared.global [%0], [%1], 16;" :: "r"(dst), "l"(src))
#define CPA_COMMIT() asm volatile("cp.async.commit_group;")
#define CPA_WAIT1()  asm volatile("cp.async.wait_group 1;")
#define CPA_WAIT0()  asm volatile("cp.async.wait_group 0;")

// ---- FFMA-only activations (rel err ~1.5e-7) ----
__device__ __forceinline__ float fsig(float x) {
    float u = fminf(fmaxf(-1.4426950408889634f * x, -80.f), 80.f);
    int e = __float2int_rn(u);
    float f = u - (float)e;
    float p = fmaf(1.5403530e-4f, f, 1.3333558e-3f);
    p = fmaf(p, f, 9.6181291e-3f);
    p = fmaf(p, f, 5.5504109e-2f);
    p = fmaf(p, f, 2.4022651e-1f);
    p = fmaf(p, f, 6.9314718e-1f);
    p = fmaf(p, f, 1.0f);
    float s = __int_as_float((e + 127) << 23);
    float den = fmaf(p, s, 1.0f);
    float r = __int_as_float(0x7EF311C3 - __float_as_int(den));
    r = r * fmaf(-den, r, 2.0f);
    r = r * fmaf(-den, r, 2.0f);
    r = r * fmaf(-den, r, 2.0f);
    return r;
}
__device__ __forceinline__ float ftanh(float x) {
    return fmaf(2.0f, fsig(2.0f * x), -1.0f);
}

// ---- grid barrier: atomic arrival, volatile-load polling ----
__device__ __forceinline__ void gbar() {
    __syncthreads();
    if (threadIdx.x == 0) {
        __threadfence();
        unsigned gen = *(volatile unsigned*)&g_bar_gen;
        if (atomicAdd(&g_bar_cnt, 1u) == NBLK - 1) {
            atomicExch(&g_bar_cnt, 0u);
            __threadfence();
            atomicAdd(&g_bar_gen, 1u);
        } else {
            while (*(volatile unsigned*)&g_bar_gen == gen) {}
        }
        __threadfence();
    }
    __syncthreads();
}

// ---------------- weight packing (fp32 for xproj, biases) ----------------
__global__ void k_pack(const float* __restrict__ Wih0,
                       const float* __restrict__ bih0, const float* __restrict__ bhh0,
                       const float* __restrict__ bih1, const float* __restrict__ bhh1) {
    int region = blockIdx.y;
    long i = (long)blockIdx.x * blockDim.x + threadIdx.x;
    if (region == 0) {
        if (i >= 2L * Ed * G4) return;
        int d = (int)(i / (Ed * G4)); int rem = (int)(i % (Ed * G4));
        int k = rem / G4, n = rem % G4;
        int h = n >> 2, g = n & 3;
        g_WihP0[d][k][n] = Wih0[((long)d * G4 + g * Hd + h) * Ed + k];
    } else if (region == 1) {
        if (i >= 2L * G4) return;
        int d = (int)(i / G4); int n = (int)(i % G4);
        int h = n >> 2, g = n & 3;
        long j = (long)d * G4 + g * Hd + h;
        g_bP0[d][n] = bih0[j] + bhh0[j];
    } else {
        if (i >= 2L * G4) return;
        int d = (int)(i / G4); int n = (int)(i % G4);
        int h = n >> 2, g = n & 3;
        long j = (long)d * G4 + g * Hd + h;
        g_bP1[d][n] = bih1[j] + bhh1[j];
    }
}

// ---------------- fp16 weight packing (single, gate-interleaved) ----------------
__global__ void k_packbf(const float* __restrict__ Wfc, const float* __restrict__ Wih1,
                         const float* __restrict__ Whh0, const float* __restrict__ Whh1) {
    long i = (long)blockIdx.x * blockDim.x + threadIdx.x;
    if (blockIdx.y == 0) {
        if (i >= (long)Vd * Kfc) return;
        g_WfcH[i] = __float2half(Wfc[i]);
    } else if (blockIdx.y == 1) {
        if (i >= 2L * G4 * Kfc) return;
        int d = (int)(i / (G4 * Kfc)); long rem = i % ((long)G4 * Kfc);
        int n = (int)(rem / Kfc), k = (int)(rem % Kfc);
        int h = n >> 2, g = n & 3;
        g_W1H[i] = __float2half(Wih1[((long)d * G4 + g * Hd + h) * Kfc + k]);
    } else {
        if (i >= 2L * 2 * G4 * Hd) return;
        int lay = (int)(i / (2L * G4 * Hd));
        long rem = i % (2L * G4 * Hd);
        int d = (int)(rem / ((long)G4 * Hd));
        long r2 = rem % ((long)G4 * Hd);
        int n = (int)(r2 / Hd), k = (int)(r2 % Hd);
        int h = n >> 2, g = n & 3;
        const float* W = lay ? Whh1 : Whh0;
        g_WsH[lay][d][n][k] = __float2half(W[((long)d * G4 + g * Hd + h) * Hd + k]);
    }
}

// ---------------- initial states: fp16 hi/lo h0, fp32 c0 ----------------
__global__ void k_init(const float* __restrict__ img, const float* __restrict__ Wh,
                       const float* __restrict__ bh, const float* __restrict__ Wc,
                       const float* __restrict__ bc) {
    int i = blockIdx.x * blockDim.x + threadIdx.x;
    if (i >= 2 * Bd * Hd) return;
    int which = i / (Bd * Hd);
    int rem = i % (Bd * Hd);
    int b = rem / Hd, j = rem % Hd;
    const float* W = which ? Wc : Wh;
    const float* bias = which ? bc : bh;
    const float4* a4 = (const float4*)(img + (long)b * CNNd);
    const float4* w4 = (const float4*)(W + (long)j * CNNd);
    float acc = 0.f;
#pragma unroll 4
    for (int k = 0; k < CNNd / 4; k++) {
        float4 a = a4[k], w = w4[k];
        acc += a.x * w.x + a.y * w.y + a.z * w.z + a.w * w.w;
    }
    float v = fmaxf(acc + bias[j], 0.f);
    __half hv = __float2half(v);
    __half lv = __float2half(v - __half2float(hv));
    for (int nc = 0; nc < NCd; nc++) {
        int row = nc * Bd + b;
        for (int l = 0; l < 2; l++)
            for (int d = 0; d < 2; d++) {
                if (which == 0) { g_hbH[0][l][d][row][j] = hv; g_hbL[0][l][d][row][j] = lv; }
                else            g_cS[l][d][row][j] = v;
            }
    }
}

// ---------------- layer0 input projections for all t (fp32 FFMA) ----------------
__global__ void k_xproj(const float* __restrict__ emb, const int* __restrict__ cap) {
    __shared__ float xs[32 * Ed];
    __shared__ int toks[32];
    int bm = blockIdx.x, bn = blockIdx.y, d = blockIdx.z;
    int tid = threadIdx.x;
    if (tid < 32) {
        int m = bm * 32 + tid;
        int t = m / Rd, r = m % Rd;
        int nc = r >> 5, b = r & 31;
        toks[tid] = cap[b * (NCd * Td) + nc * Td + t];
    }
    __syncthreads();
    for (int e = tid; e < 32 * Ed; e += 256) {
        int lr = e / Ed, k = e % Ed;
        xs[e] = emb[(long)toks[lr] * Ed + k];
    }
    __syncthreads();
    int tx = tid & 31, ty = tid >> 5;
    float acc[4][4];
#pragma unroll
    for (int a = 0; a < 4; a++)
#pragma unroll
        for (int c = 0; c < 4; c++) acc[a][c] = 0.f;
    int n0 = bn * 128;
    const float* Bp = &g_WihP0[d][0][0];
#pragma unroll 5
    for (int k = 0; k < Ed; k++) {
        float av[4], bv[4];
#pragma unroll
        for (int jr = 0; jr < 4; jr++) av[jr] = xs[(ty + jr * 8) * Ed + k];
#pragma unroll
        for (int jc = 0; jc < 4; jc++) bv[jc] = Bp[(long)k * G4 + n0 + tx + jc * 32];
#pragma unroll
        for (int jr = 0; jr < 4; jr++)
#pragma unroll
            for (int jc = 0; jc < 4; jc++) acc[jr][jc] += av[jr] * bv[jc];
    }
    int m0 = bm * 32;
#pragma unroll
    for (int jr = 0; jr < 4; jr++) {
        int m = m0 + ty + jr * 8;
        int t = m / Rd, r = m % Rd;
#pragma unroll
        for (int jc = 0; jc < 4; jc++) {
            int n = n0 + tx + jc * 32;
            g_X0[d][t][r][n] = acc[jr][jc] + g_bP0[d][n];
        }
    }
}

// =========================================================================
// chain smem: A hi/lo double-buffered + B double-buffered (zproj-sized)
// =========================================================================
#define A_ELEMS (2 * 160 * PITCH)
#define B_ELEMS (2 * 128 * PITCH)
#define CHAIN_SMEM ((2 * A_ELEMS + B_ELEMS) * 2)

// ---- one recurrent LSTM step: block 160x64, 20 warps, warp 16x32 ----
__device__ __forceinline__ void do_step(char* dsm, int n0, int lay, int d,
                                        int p, int s, int w) {
    __half* sA_h = (__half*)dsm;
    __half* sA_l = sA_h + A_ELEMS;
    __half* sB = sA_l + A_ELEMS;
    uint32_t uAh = smem_u32(sA_h), uAl = smem_u32(sA_l), uB = smem_u32(sB);

    int tid = threadIdx.x;
    int lane = tid & 31, wid = tid >> 5;
    int wm = wid >> 1, wn = wid & 1;     // 10m x 2n

    const __half* hH = &g_hbH[p][lay][d][0][0];
    const __half* hL = &g_hbL[p][lay][d][0][0];
    __half* hoH = &g_hbH[p ^ 1][lay][d][0][0];
    __half* hoL = &g_hbL[p ^ 1][lay][d][0][0];
    float* cstp = &g_cS[lay][d][0][0];
    int xidx = d ? (w - s) : s;
    const float* Xp = lay ? &g_Z[d][xidx][0][0] : &g_X0[d][xidx][0][0];
    const __half* BH = &g_WsH[lay][d][0][0];

    int arow = tid >> 2, akoff = (tid & 3) * 8;    // 640 threads cover 160x32

    float c[4][4];
#pragma unroll
    for (int nt = 0; nt < 4; nt++)
#pragma unroll
        for (int q = 0; q < 4; q++) c[nt][q] = 0.f;

    auto ISSUE = [&](int kc, int buf) {
        int ka = kc * 32 + akoff;
        uint32_t da = (uint32_t)(buf * 160 * PITCH + arow * PITCH + akoff) * 2;
        CPA16(uAh + da, hH + arow * Hd + ka);
        CPA16(uAl + da, hL + arow * Hd + ka);
        if (tid < 256) {
            uint32_t db = (uint32_t)(buf * 64 * PITCH + arow * PITCH + akoff) * 2;
            CPA16(uB + db, BH + (long)(n0 + arow) * Hd + ka);
        }
    };

    ISSUE(0, 0); CPA_COMMIT();
    for (int kc = 0; kc < 16; kc++) {
        int buf = kc & 1;
        if (kc < 15) { ISSUE(kc + 1, buf ^ 1); CPA_COMMIT(); CPA_WAIT1(); }
        else CPA_WAIT0();
        __syncthreads();
        uint32_t boA = (uint32_t)buf * 160 * PITCH * 2;
        uint32_t boB = (uint32_t)buf * 64 * PITCH * 2;
#pragma unroll
        for (int k16 = 0; k16 < 2; k16++) {
            int ar = lane & 15;
            int acs = k16 * 16 + ((lane >> 4) << 3);
            uint32_t ah[4], al[4];
            uint32_t offa = boA + (uint32_t)((wm * 16 + ar) * PITCH + acs) * 2;
            LDSM4(ah, uAh + offa);
            LDSM4(al, uAl + offa);
            int br = (lane & 7) + ((lane >> 4) << 3);
            int bcs = k16 * 16 + (((lane >> 3) & 1) << 3);
            uint32_t bh[4][2];
#pragma unroll
            for (int ntp = 0; ntp < 2; ntp++) {
                uint32_t off = boB + (uint32_t)((wn * 32 + ntp * 16 + br) * PITCH + bcs) * 2;
                uint32_t r4[4];
                LDSM4(r4, uB + off);
                bh[ntp * 2][0] = r4[0]; bh[ntp * 2][1] = r4[1];
                bh[ntp * 2 + 1][0] = r4[2]; bh[ntp * 2 + 1][1] = r4[3];
            }
#pragma unroll
            for (int nt = 0; nt < 4; nt++) {
                MMA16816(c[nt], ah, bh[nt]);
                MMA16816(c[nt], al, bh[nt]);
            }
        }
        __syncthreads();
    }

    // ---- fused LSTM cell epilogue (FFMA-only activations, all lanes) ----
    int qrow = lane >> 2, quad = lane & 3;
    bool isIF = (quad & 1) == 0;
#pragma unroll
    for (int nt = 0; nt < 4; nt++) {
        int nbase = n0 + wn * 32 + nt * 8;
        int n = nbase + quad * 2;
        int r1 = wm * 16 + qrow;
        int r2 = r1 + 8;
        float2 x1 = *(const float2*)&Xp[(long)r1 * G4 + n];
        float2 x2 = *(const float2*)&Xp[(long)r2 * G4 + n];
        float a0 = c[nt][0] + x1.x;
        float a1 = c[nt][1] + x1.y;
        float a2 = c[nt][2] + x2.x;
        float a3 = c[nt][3] + x2.y;
        float b0 = __shfl_xor_sync(0xffffffffu, a0, 1);
        float b1 = __shfl_xor_sync(0xffffffffu, a1, 1);
        float b2 = __shfl_xor_sync(0xffffffffu, a2, 1);
        float b3 = __shfl_xor_sync(0xffffffffu, a3, 1);
        int hh = (nbase >> 2) + (quad >> 1);
        int row = isIF ? r1 : r2;
        float gi = isIF ? a0 : b2;
        float gf = isIF ? a1 : b3;
        float gg = isIF ? b0 : a2;
        float go = isIF ? b1 : a3;
        float si = fsig(gi);
        float sf = fsig(gf);
        float so = fsig(go);
        float tg = ftanh(gg);
        float cc = fmaf(sf, cstp[row * Hd + hh], si * tg);
        float h = so * ftanh(cc);
        cstp[row * Hd + hh] = cc;
        __half hb = __float2half(h);
        __half lb = __float2half(h - __half2float(hb));
        hoH[row * Hd + hh] = hb;
        hoL[row * Hd + hh] = lb;
        if (lay == 0) {
            g_hsH[d][s][row][hh] = hb;
            g_hsL[d][s][row][hh] = lb;
        }
    }
}

// ---- one zproj tile: 160x128, 20 warps, warp 16x64, K=1024 ----
__device__ __forceinline__ void do_zproj(char* dsm, int t, int d, int nt0, int w) {
    __half* sA_h = (__half*)dsm;
    __half* sA_l = sA_h + A_ELEMS;
    __half* sB = sA_l + A_ELEMS;
    uint32_t uAh = smem_u32(sA_h), uAl = smem_u32(sA_l), uB = smem_u32(sB);

    int tid = threadIdx.x;
    int lane = tid & 31, wid = tid >> 5;
    int wm = wid >> 1, wn = wid & 1;
    int n0 = nt0 * 128;
    int tb = w - t;

    int arow = tid >> 2, akoff = (tid & 3) * 8;

    float c[8][4];
#pragma unroll
    for (int nt = 0; nt < 8; nt++)
#pragma unroll
        for (int q = 0; q < 4; q++) c[nt][q] = 0.f;

    auto ISSUE = [&](int kc, int buf) {
        int ka = kc * 32 + akoff;
        const __half* pH = (ka < Hd) ? &g_hsH[0][t][arow][ka]
                                     : &g_hsH[1][tb][arow][ka - Hd];
        const __half* pL = (ka < Hd) ? &g_hsL[0][t][arow][ka]
                                     : &g_hsL[1][tb][arow][ka - Hd];
        uint32_t da = (uint32_t)(buf * 160 * PITCH + arow * PITCH + akoff) * 2;
        CPA16(uAh + da, pH);
        CPA16(uAl + da, pL);
        if (tid < 512) {
            uint32_t db = (uint32_t)(buf * 128 * PITCH + arow * PITCH + akoff) * 2;
            CPA16(uB + db, g_W1H + ((long)d * G4 + n0 + arow) * Kfc + ka);
        }
    };

    ISSUE(0, 0); CPA_COMMIT();
    for (int kc = 0; kc < 32; kc++) {
        int buf = kc & 1;
        if (kc < 31) { ISSUE(kc + 1, buf ^ 1); CPA_COMMIT(); CPA_WAIT1(); }
        else CPA_WAIT0();
        __syncthreads();
        uint32_t boA = (uint32_t)buf * 160 * PITCH * 2;
        uint32_t boB = (uint32_t)buf * 128 * PITCH * 2;
#pragma unroll
        for (int k16 = 0; k16 < 2; k16++) {
            int ar = lane & 15;
            int acs = k16 * 16 + ((lane >> 4) << 3);
            uint32_t ah[4], al[4];
            uint32_t offa = boA + (uint32_t)((wm * 16 + ar) * PITCH + acs) * 2;
            LDSM4(ah, uAh + offa);
            LDSM4(al, uAl + offa);
            int br = (lane & 7) + ((lane >> 4) << 3);
            int bcs = k16 * 16 + (((lane >> 3) & 1) << 3);
            uint32_t bh[8][2];
#pragma unroll
            for (int ntp = 0; ntp < 4; ntp++) {
                uint32_t off = boB + (uint32_t)((wn * 64 + ntp * 16 + br) * PITCH + bcs) * 2;
                uint32_t r4[4];
                LDSM4(r4, uB + off);
                bh[ntp * 2][0] = r4[0]; bh[ntp * 2][1] = r4[1];
                bh[ntp * 2 + 1][0] = r4[2]; bh[ntp * 2 + 1][1] = r4[3];
            }
#pragma unroll
            for (int nt = 0; nt < 8; nt++) {
                MMA16816(c[nt], ah, bh[nt]);
                MMA16816(c[nt], al, bh[nt]);
            }
        }
        __syncthreads();
    }

    int qrow = lane >> 2, qcol = (lane & 3) * 2;
#pragma unroll
    for (int nt = 0; nt < 8; nt++) {
        int n = n0 + wn * 64 + nt * 8 + qcol;
        float2 bb = *(const float2*)&g_bP1[d][n];
        int r1 = wm * 16 + qrow;
        int r2 = r1 + 8;
        *(float2*)&g_Z[d][t][r1][n] =
            make_float2(c[nt][0] + bb.x, c[nt][1] + bb.y);
        *(float2*)&g_Z[d][t][r2][n] =
            make_float2(c[nt][2] + bb.x, c[nt][3] + bb.y);
    }
}

__device__ __forceinline__ void do_packst(int bid, int w, int pb) {
    for (int i = bid * CTH + threadIdx.x; i < Rd * 2 * Hd; i += NBLK * CTH) {
        int r = i / (2 * Hd), k = i % (2 * Hd);
        int nc = r >> 5, b = r & 31;
        __half hv, lv;
        if (k < Hd) { hv = g_hbH[pb][1][1][r][k]; lv = g_hbL[pb][1][1][r][k]; }
        else        { hv = g_hbH[pb][1][0][r][k - Hd]; lv = g_hbL[pb][1][0][r][k - Hd]; }
        int m = (nc * Td + w) * Bd + b;
        g_packedH[m][k] = hv;
        g_packedL[m][k] = lv;
    }
}

// =========================================================================
// persistent chain: whole recurrent schedule in ONE launch (128 blocks)
// =========================================================================
__global__ void __launch_bounds__(CTH, 1) k_chain() {
    extern __shared__ __align__(16) char dsm[];
    int bid = blockIdx.x;
    int z = bid >> 5, lay_b = z >> 1, d_b = z & 1;
    int n0_b = (bid & 31) * 64;
    int p0 = 0, p1 = 0;

    if (lay_b == 0) do_step(dsm, n0_b, 0, d_b, p0, 0, 0);
    p0 ^= 1;
    gbar();
    for (int tile = bid; tile < 32; tile += NBLK) {
        int t = tile >> 5, d = (tile >> 4) & 1, nt = tile & 15;
        do_zproj(dsm, t, d, nt, 0);
    }
    gbar();

    for (int w = 0; w < Td; w++) {
        int s0max = (w + 1 < Td) ? (w + 1) : -1;
        int s1max = w;
        int smax = s0max > s1max ? s0max : s1max;
        for (int s = 0; s <= smax; s++) {
            int a0 = (s <= s0max) ? 1 : 0;
            int a1 = (s <= s1max) ? 1 : 0;
            int act = lay_b ? a1 : a0;
            if (act) {
                if (lay_b == 0) do_step(dsm, n0_b, 0, d_b, p0, s, w + 1);
                else            do_step(dsm, n0_b, 1, d_b, p1, s, w);
            }
            if (a0) p0 ^= 1;
            if (a1) p1 ^= 1;
            gbar();
        }
        do_packst(bid, w, p1);
        if (w + 1 < Td) {
            int ntiles = (w + 2) * 32;
            for (int tile = bid; tile < ntiles; tile += NBLK) {
                int t = tile >> 5, d = (tile >> 4) & 1, nt = tile & 15;
                do_zproj(dsm, t, d, nt, w + 1);
            }
        }
        gbar();
    }
}

// =========================================================================
// final vocab projection (2-term fp16 mma.sync, unchanged): grid (25, 239)
// =========================================================================
#define FB_ELEMS (2 * 128 * PITCH)
__global__ void __launch_bounds__(256)
k_mma(const float* __restrict__ bfc, float* __restrict__ out) {
    extern __shared__ __align__(16) char dsm[];
    __half* sA_h = (__half*)dsm;
    __half* sA_l = sA_h + FB_ELEMS;
    __half* sB_h = sA_l + FB_ELEMS;
    uint32_t uAh = smem_u32(sA_h), uAl = smem_u32(sA_l);
    uint32_t uBh = smem_u32(sB_h);

    int tid = threadIdx.x;
    int lane = tid & 31, wid = tid >> 5;
    int wm = wid >> 1, wn = wid & 1;
    int m0 = blockIdx.x * 128, n0 = blockIdx.y * 128;

    int sr = tid & 127, kh = tid >> 7;
    int k0 = kh * 16;

    int am = m0 + sr;
    const __half* aH0 = &g_packedH[am][0];
    const __half* aL0 = &g_packedL[am][0];

    int bnr = n0 + sr;
    bool bvalid = (bnr < Vd);
    long boff = (long)bnr * Kfc;

    float c[2][8][4];
#pragma unroll
    for (int mt = 0; mt < 2; mt++)
#pragma unroll
        for (int nt = 0; nt < 8; nt++)
#pragma unroll
            for (int q = 0; q < 4; q++) c[mt][nt][q] = 0.f;

    uint4 vA[4], vB[2];

    auto LOAD = [&](int kc) {
        int kb = kc * 32 + k0;
        vA[0] = *(const uint4*)(aH0 + kb);
        vA[1] = *(const uint4*)(aH0 + kb + 8);
        vA[2] = *(const uint4*)(aL0 + kb);
        vA[3] = *(const uint4*)(aL0 + kb + 8);
        if (bvalid) {
            vB[0] = *(const uint4*)(g_WfcH + boff + kb);
            vB[1] = *(const uint4*)(g_WfcH + boff + kb + 8);
        } else {
            uint4 zz = make_uint4(0, 0, 0, 0);
            vB[0] = zz; vB[1] = zz;
        }
    };
    auto STORE = [&](int buf) {
        int base = buf * 128 * PITCH + sr * PITCH + k0;
        *(uint4*)&sA_h[base] = vA[0]; *(uint4*)&sA_h[base + 8] = vA[1];
        *(uint4*)&sA_l[base] = vA[2]; *(uint4*)&sA_l[base + 8] = vA[3];
        *(uint4*)&sB_h[base] = vB[0]; *(uint4*)&sB_h[base + 8] = vB[1];
    };
    auto COMPUTE = [&](int buf) {
        uint32_t bo = (uint32_t)buf * 128 * PITCH * 2;
#pragma unroll
        for (int k16 = 0; k16 < 2; k16++) {
            int ar = lane & 15;
            int acs = k16 * 16 + ((lane >> 4) << 3);
            uint32_t ah[2][4], al[2][4];
#pragma unroll
            for (int mt = 0; mt < 2; mt++) {
                uint32_t off = bo + (uint32_t)((wm * 32 + mt * 16 + ar) * PITCH + acs) * 2;
                LDSM4(ah[mt], uAh + off);
                LDSM4(al[mt], uAl + off);
            }
            int br = (lane & 7) + ((lane >> 4) << 3);
            int bcs = k16 * 16 + (((lane >> 3) & 1) << 3);
            uint32_t bh[8][2];
#pragma unroll
            for (int ntp = 0; ntp < 4; ntp++) {
                uint32_t off = bo + (uint32_t)((wn * 64 + ntp * 16 + br) * PITCH + bcs) * 2;
                uint32_t r4[4];
                LDSM4(r4, uBh + off);
                bh[ntp * 2][0] = r4[0]; bh[ntp * 2][1] = r4[1];
                bh[ntp * 2 + 1][0] = r4[2]; bh[ntp * 2 + 1][1] = r4[3];
            }
#pragma unroll
            for (int mt = 0; mt < 2; mt++)
#pragma unroll
                for (int nt = 0; nt < 8; nt++) {
                    MMA16816(c[mt][nt], ah[mt], bh[nt]);
                    MMA16816(c[mt][nt], al[mt], bh[nt]);
                }
        }
    };

    LOAD(0); STORE(0);
    __syncthreads();
    for (int kc = 0; kc < 32; kc++) {
        int buf = kc & 1;
        if (kc < 31) LOAD(kc + 1);
        COMPUTE(buf);
        if (kc < 31) STORE(buf ^ 1);
        __syncthreads();
    }

    int qrow = lane >> 2, qcol = (lane & 3) * 2;
#pragma unroll
    for (int mt = 0; mt < 2; mt++) {
#pragma unroll
        for (int nt = 0; nt < 8; nt++) {
            int n = n0 + wn * 64 + nt * 8 + qcol;
            int mA = m0 + wm * 32 + mt * 16 + qrow;
            if (n < Vd) {
                float2 bb = *(const float2*)&bfc[n];
                *(float2*)&out[(long)mA * Vd + n] =
                    make_float2(c[mt][nt][0] + bb.x, c[mt][nt][1] + bb.y);
                *(float2*)&out[(long)(mA + 8) * Vd + n] =
                    make_float2(c[mt][nt][2] + bb.x, c[mt][nt][3] + bb.y);
            }
        }
    }
}

// ---------------- host orchestration (6 graph nodes) ----------------
#define MMA_SMEM (3 * FB_ELEMS * 2)   // 61440 bytes

extern "C" void kernel_launch(void* const* d_in, const int* in_sizes, int n_in,
                              void* d_out, int out_size) {
    const float* img  = (const float*)d_in[0];
    const int*   cap  = (const int*)d_in[1];
    const float* emb  = (const float*)d_in[2];
    const float* Wh   = (const float*)d_in[3];
    const float* bh   = (const float*)d_in[4];
    const float* Wc   = (const float*)d_in[5];
    const float* bc   = (const float*)d_in[6];
    const float* Wih0 = (const float*)d_in[7];
    const float* Whh0 = (const float*)d_in[8];
    const float* bih0 = (const float*)d_in[9];
    const float* bhh0 = (const float*)d_in[10];
    const float* Wih1 = (const float*)d_in[11];
    const float* Whh1 = (const float*)d_in[12];
    const float* bih1 = (const float*)d_in[13];
    const float* bhh1 = (const float*)d_in[14];
    const float* Wfc  = (const float*)d_in[15];
    const float* bfc  = (const float*)d_in[16];
    float* out = (float*)d_out;

    cudaFuncSetAttribute(k_mma, cudaFuncAttributeMaxDynamicSharedMemorySize, MMA_SMEM);
    cudaFuncSetAttribute(k_chain, cudaFuncAttributeMaxDynamicSharedMemorySize, CHAIN_SMEM);

    k_pack<<<dim3(4000, 3), 256>>>(Wih0, bih0, bhh0, bih1, bhh1);
    k_packbf<<<dim3(122088, 3), 256>>>(Wfc, Wih1, Whh0, Whh1);
    k_init<<<(2 * Bd * Hd + 255) / 256, 256>>>(img, Wh, bh, Wc, bc);
    k_xproj<<<dim3(100, 16, 2), 256>>>(emb, cap);
    k_chain<<<NBLK, CTH, CHAIN_SMEM>>>();
    k_mma<<<dim3(25, 239), 256, MMA_SMEM>>>(bfc, out);
}